// round 3
// baseline (speedup 1.0000x reference)
#include <cuda_runtime.h>
#include <math.h>

#define BATCH 4
#define LEN   4096
#define DIN   2048
#define NST   16
#define RNK   128
#define M_TOT (BATCH*LEN)   // 16384
#define CHUNK 16
#define NCH   (LEN/CHUNK)   // 256

// Scratch (device globals: no allocation allowed in kernel_launch)
__device__ float g_dt[(size_t)M_TOT * RNK];       // 8 MB
__device__ float g_B [(size_t)M_TOT * NST];       // 1 MB
__device__ float g_C [(size_t)M_TOT * NST];       // 1 MB
__device__ float g_delta[(size_t)M_TOT * DIN];    // 128 MB

// ---------------------------------------------------------------------------
// GEMM1: x_dbl[m, n] = sum_k X[m,k] * W[n,k],  M=16384, N=160, K=2048
// ---------------------------------------------------------------------------
__global__ __launch_bounds__(256) void gemm1_kernel(
    const float* __restrict__ X, const float* __restrict__ W)
{
    __shared__ float Xs[32][65];    // [k][m], padded
    __shared__ float Ws[32][161];   // [k][n], padded

    const int tid  = threadIdx.x;
    const int lane = tid & 31;
    const int grp  = tid >> 5;
    const int m0   = blockIdx.x * 64;

    float acc[8][5];
#pragma unroll
    for (int i = 0; i < 8; i++)
#pragma unroll
        for (int j = 0; j < 5; j++) acc[i][j] = 0.f;

    for (int k0 = 0; k0 < DIN; k0 += 32) {
        __syncthreads();
#pragma unroll
        for (int q = 0; q < 2; q++) {
            int id  = q * 256 + tid;
            int row = id >> 3;
            int kc  = (id & 7) * 4;
            float4 v = *(const float4*)(X + (size_t)(m0 + row) * DIN + k0 + kc);
            Xs[kc + 0][row] = v.x; Xs[kc + 1][row] = v.y;
            Xs[kc + 2][row] = v.z; Xs[kc + 3][row] = v.w;
        }
#pragma unroll
        for (int q = 0; q < 5; q++) {
            int id   = q * 256 + tid;
            int nrow = id >> 3;
            int kc   = (id & 7) * 4;
            float4 v = *(const float4*)(W + (size_t)nrow * DIN + k0 + kc);
            Ws[kc + 0][nrow] = v.x; Ws[kc + 1][nrow] = v.y;
            Ws[kc + 2][nrow] = v.z; Ws[kc + 3][nrow] = v.w;
        }
        __syncthreads();
#pragma unroll
        for (int kk = 0; kk < 32; kk++) {
            float xr[8], wv[5];
#pragma unroll
            for (int i = 0; i < 8; i++) xr[i] = Xs[kk][grp * 8 + i];
#pragma unroll
            for (int j = 0; j < 5; j++) wv[j] = Ws[kk][lane + 32 * j];
#pragma unroll
            for (int i = 0; i < 8; i++)
#pragma unroll
                for (int j = 0; j < 5; j++)
                    acc[i][j] = fmaf(xr[i], wv[j], acc[i][j]);
        }
    }

#pragma unroll
    for (int i = 0; i < 8; i++) {
        const int m = m0 + grp * 8 + i;
#pragma unroll
        for (int j = 0; j < 5; j++) {
            const int c = lane + 32 * j;
            const float v = acc[i][j];
            if (c < RNK)            g_dt[(size_t)m * RNK + c]            = v;
            else if (c < RNK + NST) g_B [(size_t)m * NST + (c - RNK)]    = v;
            else                    g_C [(size_t)m * NST + (c - RNK - NST)] = v;
        }
    }
}

// ---------------------------------------------------------------------------
// GEMM2: delta[m,d] = softplus( sum_r dt[m,r] * Wd[d,r] + bias[d] )
// ---------------------------------------------------------------------------
__global__ __launch_bounds__(256) void gemm2_kernel(
    const float* __restrict__ Wd, const float* __restrict__ bias)
{
    __shared__ float Ts[32][65];
    __shared__ float Ws[32][129];

    const int tid  = threadIdx.x;
    const int lane = tid & 31;
    const int grp  = tid >> 5;
    const int m0   = (blockIdx.x & 255) * 64;
    const int d0   = (blockIdx.x >> 8) * 128;

    float acc[8][4];
#pragma unroll
    for (int i = 0; i < 8; i++)
#pragma unroll
        for (int j = 0; j < 4; j++) acc[i][j] = 0.f;

    for (int k0 = 0; k0 < RNK; k0 += 32) {
        __syncthreads();
#pragma unroll
        for (int q = 0; q < 2; q++) {
            int id  = q * 256 + tid;
            int row = id >> 3;
            int kc  = (id & 7) * 4;
            float4 v = *(const float4*)(g_dt + (size_t)(m0 + row) * RNK + k0 + kc);
            Ts[kc + 0][row] = v.x; Ts[kc + 1][row] = v.y;
            Ts[kc + 2][row] = v.z; Ts[kc + 3][row] = v.w;
        }
#pragma unroll
        for (int q = 0; q < 4; q++) {
            int id   = q * 256 + tid;
            int nrow = id >> 3;
            int kc   = (id & 7) * 4;
            float4 v = *(const float4*)(Wd + (size_t)(d0 + nrow) * RNK + k0 + kc);
            Ws[kc + 0][nrow] = v.x; Ws[kc + 1][nrow] = v.y;
            Ws[kc + 2][nrow] = v.z; Ws[kc + 3][nrow] = v.w;
        }
        __syncthreads();
#pragma unroll
        for (int kk = 0; kk < 32; kk++) {
            float xr[8], wv[4];
#pragma unroll
            for (int i = 0; i < 8; i++) xr[i] = Ts[kk][grp * 8 + i];
#pragma unroll
            for (int j = 0; j < 4; j++) wv[j] = Ws[kk][lane + 32 * j];
#pragma unroll
            for (int i = 0; i < 8; i++)
#pragma unroll
                for (int j = 0; j < 4; j++)
                    acc[i][j] = fmaf(xr[i], wv[j], acc[i][j]);
        }
    }

#pragma unroll
    for (int i = 0; i < 8; i++) {
        const int m = m0 + grp * 8 + i;
#pragma unroll
        for (int j = 0; j < 4; j++) {
            const int d = d0 + lane + 32 * j;
            float z  = acc[i][j] + bias[d];
            float sp = (z > 20.f) ? z : log1pf(__expf(z));
            g_delta[(size_t)m * DIN + d] = sp;
        }
    }
}

// ---------------------------------------------------------------------------
// Scan v3: block = 32 channels x 8 threads (2 states each).
// CHUNK=16 timesteps staged through shared memory with coalesced 128B loads.
// Software pipeline: prefetch chunk c+1 into regs, compute chunk c from smem,
// barrier, STS c+1 + coalesced out-store of c, barrier.
// Fast path (A_log == log(1..16)): e1 = e0 * exp(-delta) obtained via shfl
// from the ng=0 lane (A0 = -1), saving one MUFU per state-pair per step.
// ---------------------------------------------------------------------------
__global__ __launch_bounds__(256) void scan_kernel(
    const float* __restrict__ x, const float* __restrict__ A_log,
    const float* __restrict__ Dpar, float* __restrict__ out)
{
    __shared__ float xs [CHUNK][32];
    __shared__ float dsm[CHUNK][32];
    __shared__ float Bs [CHUNK][16];
    __shared__ float Cs [CHUNK][16];
    __shared__ float ys [CHUNK][32];

    const int tid  = threadIdx.x;
    const int lane = tid & 31;
    const int ch   = tid >> 3;            // 0..31
    const int ng   = tid & 7;             // state-pair index
    const int b    = blockIdx.x >> 6;     // 4 batches
    const int d0   = (blockIdx.x & 63) << 5;
    const int d    = d0 + ch;

    const float2 al = *(const float2*)(A_log + (size_t)d * NST + ng * 2);
    const float A0 = -__expf(al.x);
    const float A1 = -__expf(al.y);
    const float Dd = Dpar[d];

    // Warp-uniform fast-path check: A0 == -(2ng+1), A1 == -(2ng+2)
    const float n0 = (float)(2 * ng + 1);
    bool ok = (fabsf(A0 + n0) < 1e-4f * n0) && (fabsf(A1 + n0 + 1.f) < 1e-4f * n0);
    const unsigned fast = __all_sync(0xffffffffu, ok);
    const int srcLane = lane & 24;        // ng==0 lane of this channel group

    const float* xg = x       + (size_t)b * LEN * DIN + d0;
    const float* dg = g_delta + (size_t)b * LEN * DIN + d0;
    const float* Bg = g_B     + (size_t)b * LEN * NST;
    const float* Cg = g_C     + (size_t)b * LEN * NST;
    float*       og = out     + (size_t)b * LEN * DIN + d0;

    // per-thread load roles
    const int rA = (tid & 127) >> 3;      // row for x/delta tile (0..15)
    const int qA = (tid & 7) * 4;         // col for x/delta tile
    const int rB = (tid & 63) >> 2;       // row for B/C tile (0..15)
    const int qB = (tid & 3) * 4;         // col for B/C tile

    float h0 = 0.f, h1 = 0.f;
    float4 pa, pb;

    // prologue: load chunk 0
    if (tid < 128) pa = *(const float4*)(xg + (size_t)rA * DIN + qA);
    else           pa = *(const float4*)(dg + (size_t)rA * DIN + qA);
    if (tid < 64)       pb = *(const float4*)(Bg + (size_t)rB * NST + qB);
    else if (tid < 128) pb = *(const float4*)(Cg + (size_t)rB * NST + qB);

    if (tid < 128) *(float4*)&xs [rA][qA] = pa;
    else           *(float4*)&dsm[rA][qA] = pa;
    if (tid < 64)       *(float4*)&Bs[rB][qB] = pb;
    else if (tid < 128) *(float4*)&Cs[rB][qB] = pb;
    __syncthreads();

    for (int c = 0; c < NCH; c++) {
        // prefetch chunk c+1
        if (c + 1 < NCH) {
            const size_t off = (size_t)(c + 1) * CHUNK;
            if (tid < 128) pa = *(const float4*)(xg + (off + rA) * DIN + qA);
            else           pa = *(const float4*)(dg + (off + rA) * DIN + qA);
            if (tid < 64)       pb = *(const float4*)(Bg + (off + rB) * NST + qB);
            else if (tid < 128) pb = *(const float4*)(Cg + (off + rB) * NST + qB);
        }

        // compute chunk c from smem
#pragma unroll
        for (int j = 0; j < CHUNK; j++) {
            const float xv = xs [j][ch];
            const float dv = dsm[j][ch];
            const float2 Bv = *(const float2*)&Bs[j][2 * ng];
            const float2 Cv = *(const float2*)&Cs[j][2 * ng];

            float e0, e1;
            if (fast) {
                e0 = __expf(dv * A0);
                const float r = __shfl_sync(0xffffffffu, e0, srcLane);
                e1 = e0 * r;
            } else {
                e0 = __expf(dv * A0);
                e1 = __expf(dv * A1);
            }
            const float s = dv * xv;
            h0 = fmaf(e0, h0, s * Bv.x);
            h1 = fmaf(e1, h1, s * Bv.y);
            float y = fmaf(h0, Cv.x, h1 * Cv.y);
            y += __shfl_xor_sync(0xffffffffu, y, 1);
            y += __shfl_xor_sync(0xffffffffu, y, 2);
            y += __shfl_xor_sync(0xffffffffu, y, 4);
            if (ng == 0) ys[j][ch] = fmaf(Dd, xv, y);
        }
        __syncthreads();   // compute done (smem reads + ys writes visible)

        // coalesced out-store of chunk c
        if (tid < 128) {
            const size_t off = (size_t)c * CHUNK;
            *(float4*)(og + (off + rA) * DIN + qA) = *(const float4*)&ys[rA][qA];
        }

        // stage chunk c+1 into smem
        if (c + 1 < NCH) {
            if (tid < 128) *(float4*)&xs [rA][qA] = pa;
            else           *(float4*)&dsm[rA][qA] = pa;
            if (tid < 64)       *(float4*)&Bs[rB][qB] = pb;
            else if (tid < 128) *(float4*)&Cs[rB][qB] = pb;
        }
        __syncthreads();
    }
}

// ---------------------------------------------------------------------------
// Launch
// ---------------------------------------------------------------------------
extern "C" void kernel_launch(void* const* d_in, const int* in_sizes, int n_in,
                              void* d_out, int out_size)
{
    const float* x         = (const float*)d_in[0];
    const float* A_log     = (const float*)d_in[1];
    const float* D_param   = (const float*)d_in[2];
    const float* x_proj_w  = (const float*)d_in[3];
    const float* dt_proj_w = (const float*)d_in[4];
    const float* dt_proj_b = (const float*)d_in[5];
    float* out = (float*)d_out;

    gemm1_kernel<<<M_TOT / 64, 256>>>(x, x_proj_w);
    gemm2_kernel<<<(M_TOT / 64) * (DIN / 128), 256>>>(dt_proj_w, dt_proj_b);
    scan_kernel<<<BATCH * (DIN / 32), 256>>>(x, A_log, D_param, out);
}

// round 4
// speedup vs baseline: 1.1391x; 1.1391x over previous
#include <cuda_runtime.h>
#include <math.h>

#define BATCH 4
#define LEN   4096
#define DIN   2048
#define NST   16
#define RNK   128
#define M_TOT (BATCH*LEN)   // 16384
#define SCH   16            // scan chunk
#define NCH   (LEN/SCH)     // 256

typedef unsigned long long u64;

__device__ __forceinline__ u64 pack2(float lo, float hi) {
    u64 r; asm("mov.b64 %0,{%1,%2};" : "=l"(r) : "f"(lo), "f"(hi)); return r;
}
__device__ __forceinline__ float2 unpack2(u64 v) {
    float2 f; asm("mov.b64 {%0,%1},%2;" : "=f"(f.x), "=f"(f.y) : "l"(v)); return f;
}
__device__ __forceinline__ u64 ffma2(u64 a, u64 b, u64 c) {
    u64 d; asm("fma.rn.f32x2 %0,%1,%2,%3;" : "=l"(d) : "l"(a), "l"(b), "l"(c)); return d;
}

// Scratch (device globals: no allocation allowed in kernel_launch)
__device__ float g_dt[(size_t)M_TOT * RNK];       // 8 MB
__device__ float g_B [(size_t)M_TOT * NST];       // 1 MB
__device__ float g_C [(size_t)M_TOT * NST];       // 1 MB
__device__ float g_delta[(size_t)M_TOT * DIN];    // 128 MB

// ---------------------------------------------------------------------------
// GEMM1: x_dbl[m, n] = sum_k X[m,k] * W[n,k],  M=16384, N=160, K=2048
// Packed f32x2 FMA: accumulators pair adjacent m-rows; x-pairs via LDS.64.
// ---------------------------------------------------------------------------
__global__ __launch_bounds__(256) void gemm1_kernel(
    const float* __restrict__ X, const float* __restrict__ W)
{
    __shared__ __align__(16) float Xs[32][66];    // [k][m], even pad for LDS.64
    __shared__ __align__(16) float Ws[32][161];   // [k][n]

    const int tid  = threadIdx.x;
    const int lane = tid & 31;
    const int grp  = tid >> 5;
    const int m0   = blockIdx.x * 64;

    u64 acc2[4][5];
#pragma unroll
    for (int p = 0; p < 4; p++)
#pragma unroll
        for (int j = 0; j < 5; j++) acc2[p][j] = 0ull;

    for (int k0 = 0; k0 < DIN; k0 += 32) {
        __syncthreads();
#pragma unroll
        for (int q = 0; q < 2; q++) {
            int id  = q * 256 + tid;
            int row = id >> 3;
            int kc  = (id & 7) * 4;
            float4 v = *(const float4*)(X + (size_t)(m0 + row) * DIN + k0 + kc);
            Xs[kc + 0][row] = v.x; Xs[kc + 1][row] = v.y;
            Xs[kc + 2][row] = v.z; Xs[kc + 3][row] = v.w;
        }
#pragma unroll
        for (int q = 0; q < 5; q++) {
            int id   = q * 256 + tid;
            int nrow = id >> 3;
            int kc   = (id & 7) * 4;
            float4 v = *(const float4*)(W + (size_t)nrow * DIN + k0 + kc);
            Ws[kc + 0][nrow] = v.x; Ws[kc + 1][nrow] = v.y;
            Ws[kc + 2][nrow] = v.z; Ws[kc + 3][nrow] = v.w;
        }
        __syncthreads();
#pragma unroll
        for (int kk = 0; kk < 32; kk++) {
            u64 xp[4];
#pragma unroll
            for (int p = 0; p < 4; p++)
                xp[p] = *(const u64*)&Xs[kk][grp * 8 + 2 * p];
            u64 ww[5];
#pragma unroll
            for (int j = 0; j < 5; j++) {
                float w = Ws[kk][lane + 32 * j];
                ww[j] = pack2(w, w);
            }
#pragma unroll
            for (int p = 0; p < 4; p++)
#pragma unroll
                for (int j = 0; j < 5; j++)
                    acc2[p][j] = ffma2(xp[p], ww[j], acc2[p][j]);
        }
    }

#pragma unroll
    for (int p = 0; p < 4; p++) {
#pragma unroll
        for (int j = 0; j < 5; j++) {
            const float2 v = unpack2(acc2[p][j]);
            const int c = lane + 32 * j;
#pragma unroll
            for (int s = 0; s < 2; s++) {
                const int m = m0 + grp * 8 + 2 * p + s;
                const float val = s ? v.y : v.x;
                if (c < RNK)            g_dt[(size_t)m * RNK + c]            = val;
                else if (c < RNK + NST) g_B [(size_t)m * NST + (c - RNK)]    = val;
                else                    g_C [(size_t)m * NST + (c - RNK - NST)] = val;
            }
        }
    }
}

// ---------------------------------------------------------------------------
// GEMM2: delta[m,d] = softplus( sum_r dt[m,r] * Wd[d,r] + bias[d] )
// Packed f32x2 FMA, same pairing scheme.
// ---------------------------------------------------------------------------
__global__ __launch_bounds__(256) void gemm2_kernel(
    const float* __restrict__ Wd, const float* __restrict__ bias)
{
    __shared__ __align__(16) float Ts[32][66];
    __shared__ __align__(16) float Ws[32][129];

    const int tid  = threadIdx.x;
    const int lane = tid & 31;
    const int grp  = tid >> 5;
    const int m0   = (blockIdx.x & 255) * 64;
    const int d0   = (blockIdx.x >> 8) * 128;

    u64 acc2[4][4];
#pragma unroll
    for (int p = 0; p < 4; p++)
#pragma unroll
        for (int j = 0; j < 4; j++) acc2[p][j] = 0ull;

    for (int k0 = 0; k0 < RNK; k0 += 32) {
        __syncthreads();
#pragma unroll
        for (int q = 0; q < 2; q++) {
            int id  = q * 256 + tid;
            int row = id >> 3;
            int kc  = (id & 7) * 4;
            float4 v = *(const float4*)(g_dt + (size_t)(m0 + row) * RNK + k0 + kc);
            Ts[kc + 0][row] = v.x; Ts[kc + 1][row] = v.y;
            Ts[kc + 2][row] = v.z; Ts[kc + 3][row] = v.w;
        }
#pragma unroll
        for (int q = 0; q < 4; q++) {
            int id   = q * 256 + tid;
            int nrow = id >> 3;
            int kc   = (id & 7) * 4;
            float4 v = *(const float4*)(Wd + (size_t)(d0 + nrow) * RNK + k0 + kc);
            Ws[kc + 0][nrow] = v.x; Ws[kc + 1][nrow] = v.y;
            Ws[kc + 2][nrow] = v.z; Ws[kc + 3][nrow] = v.w;
        }
        __syncthreads();
#pragma unroll
        for (int kk = 0; kk < 32; kk++) {
            u64 xp[4];
#pragma unroll
            for (int p = 0; p < 4; p++)
                xp[p] = *(const u64*)&Ts[kk][grp * 8 + 2 * p];
            u64 ww[4];
#pragma unroll
            for (int j = 0; j < 4; j++) {
                float w = Ws[kk][lane + 32 * j];
                ww[j] = pack2(w, w);
            }
#pragma unroll
            for (int p = 0; p < 4; p++)
#pragma unroll
                for (int j = 0; j < 4; j++)
                    acc2[p][j] = ffma2(xp[p], ww[j], acc2[p][j]);
        }
    }

#pragma unroll
    for (int p = 0; p < 4; p++) {
#pragma unroll
        for (int j = 0; j < 4; j++) {
            const float2 v = unpack2(acc2[p][j]);
            const int d = d0 + lane + 32 * j;
            const float bv = bias[d];
#pragma unroll
            for (int s = 0; s < 2; s++) {
                const int m = m0 + grp * 8 + 2 * p + s;
                float z  = (s ? v.y : v.x) + bv;
                float sp = (z > 20.f) ? z : log1pf(__expf(z));
                g_delta[(size_t)m * DIN + d] = sp;
            }
        }
    }
}

// ---------------------------------------------------------------------------
// Scan v4: block = 64 channels x 4 threads (4 states each). 128 blocks x 256.
// Fast path (A unit-spaced, true for A=-1..-16): e0=exp(dv*A0), r=exp(-dv),
// e1=e0*r, e2=e0*r^2, e3=e1*r^2  -> 2 MUFU/thread-step instead of 4,
// and only 2 reduction shfls instead of 3 (+1).
// Smem-staged chunks of 16 timesteps; all gmem traffic coalesced float4.
// ---------------------------------------------------------------------------
__global__ __launch_bounds__(256) void scan_kernel(
    const float* __restrict__ x, const float* __restrict__ A_log,
    const float* __restrict__ Dpar, float* __restrict__ out)
{
    __shared__ __align__(16) float xs [SCH][64];
    __shared__ __align__(16) float dsm[SCH][64];
    __shared__ __align__(16) float ys [SCH][64];
    __shared__ __align__(16) float Bs [SCH][16];
    __shared__ __align__(16) float Cs [SCH][16];

    const int tid = threadIdx.x;
    const int ch  = tid >> 2;            // 0..63
    const int ng  = tid & 3;             // 4-state group
    const int b   = blockIdx.x >> 5;     // 4 batches
    const int d0  = (blockIdx.x & 31) << 6;
    const int d   = d0 + ch;

    const float4 al = *(const float4*)(A_log + (size_t)d * NST + 4 * ng);
    const float A0 = -__expf(al.x);
    const float A1 = -__expf(al.y);
    const float A2 = -__expf(al.z);
    const float A3 = -__expf(al.w);
    const float Dd = Dpar[d];

    // fast path requires unit spacing A_{i+1} = A_i - 1
    bool ok = (fabsf(A1 - A0 + 1.f) < 2e-3f) &&
              (fabsf(A2 - A1 + 1.f) < 2e-3f) &&
              (fabsf(A3 - A2 + 1.f) < 2e-3f);
    const unsigned fast = __all_sync(0xffffffffu, ok);

    const float* xg = x       + (size_t)b * LEN * DIN + d0;
    const float* dg = g_delta + (size_t)b * LEN * DIN + d0;
    const float* Bg = g_B     + (size_t)b * LEN * NST;
    const float* Cg = g_C     + (size_t)b * LEN * NST;
    float*       og = out     + (size_t)b * LEN * DIN + d0;

    // load roles
    const int rA = tid >> 4;             // 0..15 rows of 16x64 tiles
    const int qA = (tid & 15) * 4;
    const int rB = (tid & 63) >> 2;      // 0..15 rows of 16x16 tiles
    const int qB = (tid & 3) * 4;

    float h0 = 0.f, h1 = 0.f, h2 = 0.f, h3 = 0.f;
    float4 px, pd, pbc;

    // prologue: chunk 0
    px = *(const float4*)(xg + (size_t)rA * DIN + qA);
    pd = *(const float4*)(dg + (size_t)rA * DIN + qA);
    if (tid < 64)       pbc = *(const float4*)(Bg + (size_t)rB * NST + qB);
    else if (tid < 128) pbc = *(const float4*)(Cg + (size_t)rB * NST + qB);

    *(float4*)&xs [rA][qA] = px;
    *(float4*)&dsm[rA][qA] = pd;
    if (tid < 64)       *(float4*)&Bs[rB][qB] = pbc;
    else if (tid < 128) *(float4*)&Cs[rB][qB] = pbc;
    __syncthreads();

    for (int c = 0; c < NCH; c++) {
        if (c + 1 < NCH) {
            const size_t off = (size_t)(c + 1) * SCH;
            px = *(const float4*)(xg + (off + rA) * DIN + qA);
            pd = *(const float4*)(dg + (off + rA) * DIN + qA);
            if (tid < 64)       pbc = *(const float4*)(Bg + (off + rB) * NST + qB);
            else if (tid < 128) pbc = *(const float4*)(Cg + (off + rB) * NST + qB);
        }

#pragma unroll
        for (int j = 0; j < SCH; j++) {
            const float xv = xs [j][ch];
            const float dv = dsm[j][ch];
            const float4 Bv = *(const float4*)&Bs[j][4 * ng];
            const float4 Cv = *(const float4*)&Cs[j][4 * ng];

            float e0 = __expf(dv * A0), e1, e2, e3;
            if (fast) {
                const float r  = __expf(-dv);
                const float r2 = r * r;
                e1 = e0 * r;
                e2 = e0 * r2;
                e3 = e1 * r2;
            } else {
                e1 = __expf(dv * A1);
                e2 = __expf(dv * A2);
                e3 = __expf(dv * A3);
            }
            const float sb = dv * xv;
            h0 = fmaf(e0, h0, sb * Bv.x);
            h1 = fmaf(e1, h1, sb * Bv.y);
            h2 = fmaf(e2, h2, sb * Bv.z);
            h3 = fmaf(e3, h3, sb * Bv.w);
            float y = h0 * Cv.x;
            y = fmaf(h1, Cv.y, y);
            y = fmaf(h2, Cv.z, y);
            y = fmaf(h3, Cv.w, y);
            y += __shfl_xor_sync(0xffffffffu, y, 1);
            y += __shfl_xor_sync(0xffffffffu, y, 2);
            if (ng == 0) ys[j][ch] = fmaf(Dd, xv, y);
        }
        __syncthreads();

        // coalesced store of chunk c
        {
            const size_t off = (size_t)c * SCH;
            *(float4*)(og + (off + rA) * DIN + qA) = *(const float4*)&ys[rA][qA];
        }

        if (c + 1 < NCH) {
            *(float4*)&xs [rA][qA] = px;
            *(float4*)&dsm[rA][qA] = pd;
            if (tid < 64)       *(float4*)&Bs[rB][qB] = pbc;
            else if (tid < 128) *(float4*)&Cs[rB][qB] = pbc;
        }
        __syncthreads();
    }
}

// ---------------------------------------------------------------------------
// Launch
// ---------------------------------------------------------------------------
extern "C" void kernel_launch(void* const* d_in, const int* in_sizes, int n_in,
                              void* d_out, int out_size)
{
    const float* x         = (const float*)d_in[0];
    const float* A_log     = (const float*)d_in[1];
    const float* D_param   = (const float*)d_in[2];
    const float* x_proj_w  = (const float*)d_in[3];
    const float* dt_proj_w = (const float*)d_in[4];
    const float* dt_proj_b = (const float*)d_in[5];
    float* out = (float*)d_out;

    gemm1_kernel<<<M_TOT / 64, 256>>>(x, x_proj_w);
    gemm2_kernel<<<(M_TOT / 64) * (DIN / 128), 256>>>(dt_proj_w, dt_proj_b);
    scan_kernel<<<BATCH * (DIN / 64), 256>>>(x, A_log, D_param, out);
}

// round 5
// speedup vs baseline: 1.5311x; 1.3442x over previous
#include <cuda_runtime.h>
#include <math.h>

#define BATCH 4
#define LEN   4096
#define DIN   2048
#define NST   16
#define RNK   128
#define M_TOT (BATCH*LEN)   // 16384
#define SCH   16            // scan chunk (timesteps staged in smem)
#define P_SEG 16            // parallel segments
#define SEGLEN (LEN/P_SEG)  // 256
#define NCHS  (SEGLEN/SCH)  // 16 chunks per segment

typedef unsigned long long u64;

__device__ __forceinline__ u64 pack2(float lo, float hi) {
    u64 r; asm("mov.b64 %0,{%1,%2};" : "=l"(r) : "f"(lo), "f"(hi)); return r;
}
__device__ __forceinline__ float2 unpack2(u64 v) {
    float2 f; asm("mov.b64 {%0,%1},%2;" : "=f"(f.x), "=f"(f.y) : "l"(v)); return f;
}
__device__ __forceinline__ u64 ffma2(u64 a, u64 b, u64 c) {
    u64 d; asm("fma.rn.f32x2 %0,%1,%2,%3;" : "=l"(d) : "l"(a), "l"(b), "l"(c)); return d;
}

// Scratch (device globals: no allocation allowed in kernel_launch)
__device__ float g_dt[(size_t)M_TOT * RNK];       // 8 MB
__device__ float g_B [(size_t)M_TOT * NST];       // 1 MB
__device__ float g_C [(size_t)M_TOT * NST];       // 1 MB
__device__ float g_delta[(size_t)M_TOT * DIN];    // 128 MB
// segmented-scan state: [b][seg][d][n]
__device__ float g_hseg[(size_t)BATCH * P_SEG * DIN * NST];  // 8 MB
__device__ float g_pseg[(size_t)BATCH * P_SEG * DIN * NST];  // 8 MB
__device__ float g_hin [(size_t)BATCH * P_SEG * DIN * NST];  // 8 MB

// ---------------------------------------------------------------------------
// GEMM1: x_dbl[m, n] = sum_k X[m,k] * W[n,k],  M=16384, N=160, K=2048
// ---------------------------------------------------------------------------
__global__ __launch_bounds__(256) void gemm1_kernel(
    const float* __restrict__ X, const float* __restrict__ W)
{
    __shared__ __align__(16) float Xs[32][66];
    __shared__ __align__(16) float Ws[32][161];

    const int tid  = threadIdx.x;
    const int lane = tid & 31;
    const int grp  = tid >> 5;
    const int m0   = blockIdx.x * 64;

    u64 acc2[4][5];
#pragma unroll
    for (int p = 0; p < 4; p++)
#pragma unroll
        for (int j = 0; j < 5; j++) acc2[p][j] = 0ull;

    for (int k0 = 0; k0 < DIN; k0 += 32) {
        __syncthreads();
#pragma unroll
        for (int q = 0; q < 2; q++) {
            int id  = q * 256 + tid;
            int row = id >> 3;
            int kc  = (id & 7) * 4;
            float4 v = *(const float4*)(X + (size_t)(m0 + row) * DIN + k0 + kc);
            Xs[kc + 0][row] = v.x; Xs[kc + 1][row] = v.y;
            Xs[kc + 2][row] = v.z; Xs[kc + 3][row] = v.w;
        }
#pragma unroll
        for (int q = 0; q < 5; q++) {
            int id   = q * 256 + tid;
            int nrow = id >> 3;
            int kc   = (id & 7) * 4;
            float4 v = *(const float4*)(W + (size_t)nrow * DIN + k0 + kc);
            Ws[kc + 0][nrow] = v.x; Ws[kc + 1][nrow] = v.y;
            Ws[kc + 2][nrow] = v.z; Ws[kc + 3][nrow] = v.w;
        }
        __syncthreads();
#pragma unroll
        for (int kk = 0; kk < 32; kk++) {
            u64 xp[4];
#pragma unroll
            for (int p = 0; p < 4; p++)
                xp[p] = *(const u64*)&Xs[kk][grp * 8 + 2 * p];
            u64 ww[5];
#pragma unroll
            for (int j = 0; j < 5; j++) {
                float w = Ws[kk][lane + 32 * j];
                ww[j] = pack2(w, w);
            }
#pragma unroll
            for (int p = 0; p < 4; p++)
#pragma unroll
                for (int j = 0; j < 5; j++)
                    acc2[p][j] = ffma2(xp[p], ww[j], acc2[p][j]);
        }
    }

#pragma unroll
    for (int p = 0; p < 4; p++) {
#pragma unroll
        for (int j = 0; j < 5; j++) {
            const float2 v = unpack2(acc2[p][j]);
            const int c = lane + 32 * j;
#pragma unroll
            for (int s = 0; s < 2; s++) {
                const int m = m0 + grp * 8 + 2 * p + s;
                const float val = s ? v.y : v.x;
                if (c < RNK)            g_dt[(size_t)m * RNK + c]            = val;
                else if (c < RNK + NST) g_B [(size_t)m * NST + (c - RNK)]    = val;
                else                    g_C [(size_t)m * NST + (c - RNK - NST)] = val;
            }
        }
    }
}

// ---------------------------------------------------------------------------
// GEMM2: delta[m,d] = softplus( sum_r dt[m,r] * Wd[d,r] + bias[d] )
// ---------------------------------------------------------------------------
__global__ __launch_bounds__(256) void gemm2_kernel(
    const float* __restrict__ Wd, const float* __restrict__ bias)
{
    __shared__ __align__(16) float Ts[32][66];
    __shared__ __align__(16) float Ws[32][129];

    const int tid  = threadIdx.x;
    const int lane = tid & 31;
    const int grp  = tid >> 5;
    const int m0   = (blockIdx.x & 255) * 64;
    const int d0   = (blockIdx.x >> 8) * 128;

    u64 acc2[4][4];
#pragma unroll
    for (int p = 0; p < 4; p++)
#pragma unroll
        for (int j = 0; j < 4; j++) acc2[p][j] = 0ull;

    for (int k0 = 0; k0 < RNK; k0 += 32) {
        __syncthreads();
#pragma unroll
        for (int q = 0; q < 2; q++) {
            int id  = q * 256 + tid;
            int row = id >> 3;
            int kc  = (id & 7) * 4;
            float4 v = *(const float4*)(g_dt + (size_t)(m0 + row) * RNK + k0 + kc);
            Ts[kc + 0][row] = v.x; Ts[kc + 1][row] = v.y;
            Ts[kc + 2][row] = v.z; Ts[kc + 3][row] = v.w;
        }
#pragma unroll
        for (int q = 0; q < 4; q++) {
            int id   = q * 256 + tid;
            int nrow = id >> 3;
            int kc   = (id & 7) * 4;
            float4 v = *(const float4*)(Wd + (size_t)(d0 + nrow) * RNK + k0 + kc);
            Ws[kc + 0][nrow] = v.x; Ws[kc + 1][nrow] = v.y;
            Ws[kc + 2][nrow] = v.z; Ws[kc + 3][nrow] = v.w;
        }
        __syncthreads();
#pragma unroll
        for (int kk = 0; kk < 32; kk++) {
            u64 xp[4];
#pragma unroll
            for (int p = 0; p < 4; p++)
                xp[p] = *(const u64*)&Ts[kk][grp * 8 + 2 * p];
            u64 ww[4];
#pragma unroll
            for (int j = 0; j < 4; j++) {
                float w = Ws[kk][lane + 32 * j];
                ww[j] = pack2(w, w);
            }
#pragma unroll
            for (int p = 0; p < 4; p++)
#pragma unroll
                for (int j = 0; j < 4; j++)
                    acc2[p][j] = ffma2(xp[p], ww[j], acc2[p][j]);
        }
    }

#pragma unroll
    for (int p = 0; p < 4; p++) {
#pragma unroll
        for (int j = 0; j < 4; j++) {
            const float2 v = unpack2(acc2[p][j]);
            const int d = d0 + lane + 32 * j;
            const float bv = bias[d];
#pragma unroll
            for (int s = 0; s < 2; s++) {
                const int m = m0 + grp * 8 + 2 * p + s;
                float z  = (s ? v.y : v.x) + bv;
                float sp = (z > 20.f) ? z : log1pf(__expf(z));
                g_delta[(size_t)m * DIN + d] = sp;
            }
        }
    }
}

// ---------------------------------------------------------------------------
// Segmented scan PASS 1: per (b, seg, 64-channel group) run the state
// recurrence from h=0, tracking local final state L and decay product p.
// grid = 4*16*32 = 2048 blocks x 256 thr. Branch on 'fast' hoisted per chunk.
// ---------------------------------------------------------------------------
__global__ __launch_bounds__(256) void scan_seg1_kernel(
    const float* __restrict__ x, const float* __restrict__ A_log)
{
    __shared__ __align__(16) float xs [SCH][64];
    __shared__ __align__(16) float dsm[SCH][64];
    __shared__ __align__(16) float Bs [SCH][16];

    const int tid  = threadIdx.x;
    const int ch   = tid >> 2;
    const int ng   = tid & 3;
    const int dg   = blockIdx.x & 31;
    const int bseg = blockIdx.x >> 5;     // b*16+seg
    const int b    = bseg >> 4;
    const int seg  = bseg & 15;
    const int d0   = dg << 6;
    const int d    = d0 + ch;

    const float4 al = *(const float4*)(A_log + (size_t)d * NST + 4 * ng);
    const float A0 = -__expf(al.x);
    const float A1 = -__expf(al.y);
    const float A2 = -__expf(al.z);
    const float A3 = -__expf(al.w);

    bool ok = (fabsf(A1 - A0 + 1.f) < 2e-3f) &&
              (fabsf(A2 - A1 + 1.f) < 2e-3f) &&
              (fabsf(A3 - A2 + 1.f) < 2e-3f);
    const unsigned fast = __all_sync(0xffffffffu, ok);

    const size_t t0 = (size_t)b * LEN + (size_t)seg * SEGLEN;
    const float* xg = x       + t0 * DIN + d0;
    const float* dgp = g_delta + t0 * DIN + d0;
    const float* Bg = g_B     + t0 * NST;

    const int rA = tid >> 4;
    const int qA = (tid & 15) * 4;
    const int rB = (tid & 63) >> 2;
    const int qB = (tid & 3) * 4;

    float h0 = 0.f, h1 = 0.f, h2 = 0.f, h3 = 0.f;
    float p0 = 1.f, p1 = 1.f, p2 = 1.f, p3 = 1.f;
    float4 px, pd, pb;

    px = *(const float4*)(xg + (size_t)rA * DIN + qA);
    pd = *(const float4*)(dgp + (size_t)rA * DIN + qA);
    if (tid < 64) pb = *(const float4*)(Bg + (size_t)rB * NST + qB);

    *(float4*)&xs [rA][qA] = px;
    *(float4*)&dsm[rA][qA] = pd;
    if (tid < 64) *(float4*)&Bs[rB][qB] = pb;
    __syncthreads();

    for (int c = 0; c < NCHS; c++) {
        if (c + 1 < NCHS) {
            const size_t off = (size_t)(c + 1) * SCH;
            px = *(const float4*)(xg + (off + rA) * DIN + qA);
            pd = *(const float4*)(dgp + (off + rA) * DIN + qA);
            if (tid < 64) pb = *(const float4*)(Bg + (off + rB) * NST + qB);
        }

        if (fast) {
#pragma unroll
            for (int j = 0; j < SCH; j++) {
                const float xv = xs [j][ch];
                const float dv = dsm[j][ch];
                const float4 Bv = *(const float4*)&Bs[j][4 * ng];
                const float e0 = __expf(dv * A0);
                const float r  = __expf(-dv);
                const float r2 = r * r;
                const float e1 = e0 * r, e2 = e0 * r2, e3 = e1 * r2;
                const float s = dv * xv;
                h0 = fmaf(e0, h0, s * Bv.x);
                h1 = fmaf(e1, h1, s * Bv.y);
                h2 = fmaf(e2, h2, s * Bv.z);
                h3 = fmaf(e3, h3, s * Bv.w);
                p0 *= e0; p1 *= e1; p2 *= e2; p3 *= e3;
            }
        } else {
#pragma unroll
            for (int j = 0; j < SCH; j++) {
                const float xv = xs [j][ch];
                const float dv = dsm[j][ch];
                const float4 Bv = *(const float4*)&Bs[j][4 * ng];
                const float e0 = __expf(dv * A0);
                const float e1 = __expf(dv * A1);
                const float e2 = __expf(dv * A2);
                const float e3 = __expf(dv * A3);
                const float s = dv * xv;
                h0 = fmaf(e0, h0, s * Bv.x);
                h1 = fmaf(e1, h1, s * Bv.y);
                h2 = fmaf(e2, h2, s * Bv.z);
                h3 = fmaf(e3, h3, s * Bv.w);
                p0 *= e0; p1 *= e1; p2 *= e2; p3 *= e3;
            }
        }
        __syncthreads();

        if (c + 1 < NCHS) {
            *(float4*)&xs [rA][qA] = px;
            *(float4*)&dsm[rA][qA] = pd;
            if (tid < 64) *(float4*)&Bs[rB][qB] = pb;
        }
        __syncthreads();
    }

    const size_t hb = (((size_t)(b * P_SEG + seg) * DIN) + d) * NST + 4 * ng;
    *(float4*)(g_hseg + hb) = make_float4(h0, h1, h2, h3);
    *(float4*)(g_pseg + hb) = make_float4(p0, p1, p2, p3);
}

// ---------------------------------------------------------------------------
// COMBINE: serial over segments per (b,d,state-quad). h_in[seg] = state
// entering segment seg. 32768 threads = 128 blocks x 256.
// ---------------------------------------------------------------------------
__global__ __launch_bounds__(256) void scan_comb_kernel()
{
    const int tid  = threadIdx.x;
    const int cidx = blockIdx.x * 64 + (tid >> 2);   // 0..8191 = b*DIN+d
    const int ng   = tid & 3;
    const int b    = cidx >> 11;
    const int d    = cidx & (DIN - 1);

    float4 h = make_float4(0.f, 0.f, 0.f, 0.f);
#pragma unroll
    for (int s = 0; s < P_SEG; s++) {
        const size_t idx = (((size_t)(b * P_SEG + s) * DIN) + d) * NST + 4 * ng;
        *(float4*)(g_hin + idx) = h;
        const float4 Pv = *(const float4*)(g_pseg + idx);
        const float4 Lv = *(const float4*)(g_hseg + idx);
        h.x = fmaf(Pv.x, h.x, Lv.x);
        h.y = fmaf(Pv.y, h.y, Lv.y);
        h.z = fmaf(Pv.z, h.z, Lv.z);
        h.w = fmaf(Pv.w, h.w, Lv.w);
    }
}

// ---------------------------------------------------------------------------
// Segmented scan PASS 2: per (b, seg, 64-channel group), start from h_in and
// produce outputs. grid = 2048 blocks x 256 thr.
// ---------------------------------------------------------------------------
__global__ __launch_bounds__(256) void scan_seg2_kernel(
    const float* __restrict__ x, const float* __restrict__ A_log,
    const float* __restrict__ Dpar, float* __restrict__ out)
{
    __shared__ __align__(16) float xs [SCH][64];
    __shared__ __align__(16) float dsm[SCH][64];
    __shared__ __align__(16) float ys [SCH][64];
    __shared__ __align__(16) float Bs [SCH][16];
    __shared__ __align__(16) float Cs [SCH][16];

    const int tid  = threadIdx.x;
    const int ch   = tid >> 2;
    const int ng   = tid & 3;
    const int dg   = blockIdx.x & 31;
    const int bseg = blockIdx.x >> 5;
    const int b    = bseg >> 4;
    const int seg  = bseg & 15;
    const int d0   = dg << 6;
    const int d    = d0 + ch;

    const float4 al = *(const float4*)(A_log + (size_t)d * NST + 4 * ng);
    const float A0 = -__expf(al.x);
    const float A1 = -__expf(al.y);
    const float A2 = -__expf(al.z);
    const float A3 = -__expf(al.w);
    const float Dd = Dpar[d];

    bool ok = (fabsf(A1 - A0 + 1.f) < 2e-3f) &&
              (fabsf(A2 - A1 + 1.f) < 2e-3f) &&
              (fabsf(A3 - A2 + 1.f) < 2e-3f);
    const unsigned fast = __all_sync(0xffffffffu, ok);

    const size_t t0 = (size_t)b * LEN + (size_t)seg * SEGLEN;
    const float* xg = x       + t0 * DIN + d0;
    const float* dgp = g_delta + t0 * DIN + d0;
    const float* Bg = g_B     + t0 * NST;
    const float* Cg = g_C     + t0 * NST;
    float*       og = out     + t0 * DIN + d0;

    const int rA = tid >> 4;
    const int qA = (tid & 15) * 4;
    const int rB = (tid & 63) >> 2;
    const int qB = (tid & 3) * 4;

    const size_t hb = (((size_t)(b * P_SEG + seg) * DIN) + d) * NST + 4 * ng;
    const float4 h_in = *(const float4*)(g_hin + hb);
    float h0 = h_in.x, h1 = h_in.y, h2 = h_in.z, h3 = h_in.w;

    float4 px, pd, pbc;

    px = *(const float4*)(xg + (size_t)rA * DIN + qA);
    pd = *(const float4*)(dgp + (size_t)rA * DIN + qA);
    if (tid < 64)       pbc = *(const float4*)(Bg + (size_t)rB * NST + qB);
    else if (tid < 128) pbc = *(const float4*)(Cg + (size_t)rB * NST + qB);

    *(float4*)&xs [rA][qA] = px;
    *(float4*)&dsm[rA][qA] = pd;
    if (tid < 64)       *(float4*)&Bs[rB][qB] = pbc;
    else if (tid < 128) *(float4*)&Cs[rB][qB] = pbc;
    __syncthreads();

    for (int c = 0; c < NCHS; c++) {
        if (c + 1 < NCHS) {
            const size_t off = (size_t)(c + 1) * SCH;
            px = *(const float4*)(xg + (off + rA) * DIN + qA);
            pd = *(const float4*)(dgp + (off + rA) * DIN + qA);
            if (tid < 64)       pbc = *(const float4*)(Bg + (off + rB) * NST + qB);
            else if (tid < 128) pbc = *(const float4*)(Cg + (off + rB) * NST + qB);
        }

        if (fast) {
#pragma unroll
            for (int j = 0; j < SCH; j++) {
                const float xv = xs [j][ch];
                const float dv = dsm[j][ch];
                const float4 Bv = *(const float4*)&Bs[j][4 * ng];
                const float4 Cv = *(const float4*)&Cs[j][4 * ng];
                const float e0 = __expf(dv * A0);
                const float r  = __expf(-dv);
                const float r2 = r * r;
                const float e1 = e0 * r, e2 = e0 * r2, e3 = e1 * r2;
                const float s = dv * xv;
                h0 = fmaf(e0, h0, s * Bv.x);
                h1 = fmaf(e1, h1, s * Bv.y);
                h2 = fmaf(e2, h2, s * Bv.z);
                h3 = fmaf(e3, h3, s * Bv.w);
                float y = h0 * Cv.x;
                y = fmaf(h1, Cv.y, y);
                y = fmaf(h2, Cv.z, y);
                y = fmaf(h3, Cv.w, y);
                y += __shfl_xor_sync(0xffffffffu, y, 1);
                y += __shfl_xor_sync(0xffffffffu, y, 2);
                if (ng == 0) ys[j][ch] = fmaf(Dd, xv, y);
            }
        } else {
#pragma unroll
            for (int j = 0; j < SCH; j++) {
                const float xv = xs [j][ch];
                const float dv = dsm[j][ch];
                const float4 Bv = *(const float4*)&Bs[j][4 * ng];
                const float4 Cv = *(const float4*)&Cs[j][4 * ng];
                const float e0 = __expf(dv * A0);
                const float e1 = __expf(dv * A1);
                const float e2 = __expf(dv * A2);
                const float e3 = __expf(dv * A3);
                const float s = dv * xv;
                h0 = fmaf(e0, h0, s * Bv.x);
                h1 = fmaf(e1, h1, s * Bv.y);
                h2 = fmaf(e2, h2, s * Bv.z);
                h3 = fmaf(e3, h3, s * Bv.w);
                float y = h0 * Cv.x;
                y = fmaf(h1, Cv.y, y);
                y = fmaf(h2, Cv.z, y);
                y = fmaf(h3, Cv.w, y);
                y += __shfl_xor_sync(0xffffffffu, y, 1);
                y += __shfl_xor_sync(0xffffffffu, y, 2);
                if (ng == 0) ys[j][ch] = fmaf(Dd, xv, y);
            }
        }
        __syncthreads();

        {
            const size_t off = (size_t)c * SCH;
            *(float4*)(og + (off + rA) * DIN + qA) = *(const float4*)&ys[rA][qA];
        }

        if (c + 1 < NCHS) {
            *(float4*)&xs [rA][qA] = px;
            *(float4*)&dsm[rA][qA] = pd;
            if (tid < 64)       *(float4*)&Bs[rB][qB] = pbc;
            else if (tid < 128) *(float4*)&Cs[rB][qB] = pbc;
        }
        __syncthreads();
    }
}

// ---------------------------------------------------------------------------
// Launch
// ---------------------------------------------------------------------------
extern "C" void kernel_launch(void* const* d_in, const int* in_sizes, int n_in,
                              void* d_out, int out_size)
{
    const float* x         = (const float*)d_in[0];
    const float* A_log     = (const float*)d_in[1];
    const float* D_param   = (const float*)d_in[2];
    const float* x_proj_w  = (const float*)d_in[3];
    const float* dt_proj_w = (const float*)d_in[4];
    const float* dt_proj_b = (const float*)d_in[5];
    float* out = (float*)d_out;

    gemm1_kernel<<<M_TOT / 64, 256>>>(x, x_proj_w);
    gemm2_kernel<<<(M_TOT / 64) * (DIN / 128), 256>>>(dt_proj_w, dt_proj_b);
    scan_seg1_kernel<<<BATCH * P_SEG * (DIN / 64), 256>>>(x, A_log);
    scan_comb_kernel<<<BATCH * DIN / 64, 256>>>();
    scan_seg2_kernel<<<BATCH * P_SEG * (DIN / 64), 256>>>(x, A_log, D_param, out);
}

// round 7
// speedup vs baseline: 2.0938x; 1.3675x over previous
#include <cuda_runtime.h>
#include <cuda_bf16.h>
#include <math.h>
#include <stdint.h>

#define BATCH 4
#define LEN   4096
#define DIN   2048
#define NST   16
#define RNK   128
#define M_TOT (BATCH*LEN)   // 16384
#define SCH   16
#define P_SEG 16
#define SEGLEN (LEN/P_SEG)  // 256
#define NCHS  (SEGLEN/SCH)  // 16

// ---------------------------------------------------------------------------
// Device scratch
// ---------------------------------------------------------------------------
__device__ float g_B [(size_t)M_TOT * NST];
__device__ float g_C [(size_t)M_TOT * NST];
__device__ float g_delta[(size_t)M_TOT * DIN];
__device__ float g_hseg[(size_t)BATCH * P_SEG * DIN * NST];
__device__ float g_pseg[(size_t)BATCH * P_SEG * DIN * NST];
__device__ float g_hin [(size_t)BATCH * P_SEG * DIN * NST];
// bf16 hi/lo split operands (row-major, k contiguous)
__device__ __nv_bfloat16 g_w1h[(size_t)160 * DIN];
__device__ __nv_bfloat16 g_w1l[(size_t)160 * DIN];
__device__ __nv_bfloat16 g_wdh[(size_t)DIN * RNK];
__device__ __nv_bfloat16 g_wdl[(size_t)DIN * RNK];
__device__ __nv_bfloat16 g_dth[(size_t)M_TOT * RNK];
__device__ __nv_bfloat16 g_dtl[(size_t)M_TOT * RNK];

// ---------------------------------------------------------------------------
// helpers
// ---------------------------------------------------------------------------
__device__ __forceinline__ unsigned smem_u32(const void* p) {
    unsigned a;
    asm("{ .reg .u64 t; cvta.to.shared.u64 t, %1; cvt.u32.u64 %0, t; }"
        : "=r"(a) : "l"(p));
    return a;
}
__device__ __forceinline__ void split2(float a, float b, unsigned& h, unsigned& l) {
    __nv_bfloat16 ha = __float2bfloat16(a), hb = __float2bfloat16(b);
    float ra = a - __bfloat162float(ha), rb = b - __bfloat162float(hb);
    __nv_bfloat16 la = __float2bfloat16(ra), lb = __float2bfloat16(rb);
    h = (unsigned)__bfloat16_as_ushort(ha) | ((unsigned)__bfloat16_as_ushort(hb) << 16);
    l = (unsigned)__bfloat16_as_ushort(la) | ((unsigned)__bfloat16_as_ushort(lb) << 16);
}
__device__ __forceinline__ void splitf4(float4 v, uint2& h, uint2& l) {
    split2(v.x, v.y, h.x, l.x);
    split2(v.z, v.w, h.y, l.y);
}
__device__ __forceinline__ void ldsm_x4(unsigned* a, unsigned addr) {
    asm volatile("ldmatrix.sync.aligned.m8n8.x4.shared.b16 {%0,%1,%2,%3}, [%4];"
        : "=r"(a[0]), "=r"(a[1]), "=r"(a[2]), "=r"(a[3]) : "r"(addr));
}
__device__ __forceinline__ void ldsm_x2(unsigned* a, unsigned addr) {
    asm volatile("ldmatrix.sync.aligned.m8n8.x2.shared.b16 {%0,%1}, [%2];"
        : "=r"(a[0]), "=r"(a[1]) : "r"(addr));
}
__device__ __forceinline__ void mma_bf16(float* c, const unsigned* a, const unsigned* b) {
    asm volatile(
        "mma.sync.aligned.m16n8k16.row.col.f32.bf16.bf16.f32 "
        "{%0,%1,%2,%3},{%4,%5,%6,%7},{%8,%9},{%0,%1,%2,%3};"
        : "+f"(c[0]), "+f"(c[1]), "+f"(c[2]), "+f"(c[3])
        : "r"(a[0]), "r"(a[1]), "r"(a[2]), "r"(a[3]), "r"(b[0]), "r"(b[1]));
}

// ---------------------------------------------------------------------------
// PREP: split W1 (160x2048) and Wd (2048x128) into bf16 hi/lo, row-major.
// 576 blocks x 256 = 147456 float4 = exactly the data.
// ---------------------------------------------------------------------------
__global__ __launch_bounds__(256) void prep_kernel(
    const float* __restrict__ W1, const float* __restrict__ Wd)
{
    const int id = blockIdx.x * 256 + threadIdx.x;
    if (id < 81920) {                 // W1: 160 rows x 512 float4
        const int r = id >> 9, c4 = id & 511;
        float4 v = *(const float4*)(W1 + (size_t)r * DIN + c4 * 4);
        uint2 h, l; splitf4(v, h, l);
        *(uint2*)(g_w1h + (size_t)r * DIN + c4 * 4) = h;
        *(uint2*)(g_w1l + (size_t)r * DIN + c4 * 4) = l;
    } else {                          // Wd: 2048 rows x 32 float4
        const int id2 = id - 81920;
        const int r = id2 >> 5, c4 = id2 & 31;
        float4 v = *(const float4*)(Wd + (size_t)r * RNK + c4 * 4);
        uint2 h, l; splitf4(v, h, l);
        *(uint2*)(g_wdh + (size_t)r * RNK + c4 * 4) = h;
        *(uint2*)(g_wdl + (size_t)r * RNK + c4 * 4) = l;
    }
}

// ---------------------------------------------------------------------------
// GEMM1 (mma.sync bf16 split): x_dbl[M=16384, N=160] = X[M,K=2048] W[N,K]^T
// Block tile M=64, N=160, K-step 32, double-buffered. 8 warps = 2m x 4n,
// warp tile 32 x 40. Epilogue: cols<128 -> dt split bf16; 128..143 -> g_B;
// 144..159 -> g_C.
// smem per buffer: Ah/Al 64x40 bf16 (5120B each), Bh/Bl 160x40 (12800B each).
// ---------------------------------------------------------------------------
#define G1_AH 0
#define G1_AL 5120
#define G1_BH 10240
#define G1_BL 23040
#define G1_BUF 35840
#define G1_SMEM (2*G1_BUF)

__global__ __launch_bounds__(256, 2) void gemm1_kernel(const float* __restrict__ X)
{
    extern __shared__ __align__(16) char smem[];
    const unsigned sb = smem_u32(smem);
    const int tid = threadIdx.x, lane = tid & 31, w = tid >> 5;
    const int m0 = blockIdx.x * 64;
    const int wm = (w & 1) * 32;
    const int wn = (w >> 1) * 40;

    float acc[2][5][4];
#pragma unroll
    for (int i = 0; i < 2; i++)
#pragma unroll
        for (int j = 0; j < 5; j++)
#pragma unroll
            for (int q = 0; q < 4; q++) acc[i][j][q] = 0.f;

    // load roles
    const int rX0 = tid >> 3, cX0 = (tid & 7) * 4;          // X: id = tid
    const int rX1 = (tid + 256) >> 3, cX1 = cX0;            // X: id = tid+256

    float4 xr[2]; uint4 wr[5];

    auto load_regs = [&](int k0) {
        xr[0] = *(const float4*)(X + (size_t)(m0 + rX0) * DIN + k0 + cX0);
        xr[1] = *(const float4*)(X + (size_t)(m0 + rX1) * DIN + k0 + cX1);
#pragma unroll
        for (int q = 0; q < 5; q++) {
            const int id = q * 256 + tid;
            const __nv_bfloat16* src = (id < 640) ? g_w1h : g_w1l;
            const int rid = (id < 640) ? id : id - 640;
            const int r = rid >> 2, c16 = rid & 3;
            wr[q] = *(const uint4*)(src + (size_t)r * DIN + k0 + c16 * 8);
        }
    };
    auto store_smem = [&](int bi) {
        char* buf = smem + bi * G1_BUF;
        {
            uint2 h, l; splitf4(xr[0], h, l);
            *(uint2*)(buf + G1_AH + 80 * rX0 + 2 * cX0) = h;
            *(uint2*)(buf + G1_AL + 80 * rX0 + 2 * cX0) = l;
            splitf4(xr[1], h, l);
            *(uint2*)(buf + G1_AH + 80 * rX1 + 2 * cX1) = h;
            *(uint2*)(buf + G1_AL + 80 * rX1 + 2 * cX1) = l;
        }
#pragma unroll
        for (int q = 0; q < 5; q++) {
            const int id = q * 256 + tid;
            const int off = (id < 640) ? G1_BH : G1_BL;
            const int rid = (id < 640) ? id : id - 640;
            const int r = rid >> 2, c16 = rid & 3;
            *(uint4*)(buf + off + 80 * r + 16 * c16) = wr[q];
        }
    };
    auto compute = [&](int bi) {
        const unsigned base = sb + bi * G1_BUF;
#pragma unroll
        for (int ks = 0; ks < 2; ks++) {
            const int kc = ks * 16 + ((lane >> 4) & 1) * 8;       // A col
            unsigned ah[2][4], al[2][4];
#pragma unroll
            for (int mt = 0; mt < 2; mt++) {
                const int row = wm + mt * 16 + (lane & 15);
                const unsigned ad = base + 80u * row + 2u * kc;
                ldsm_x4(ah[mt], ad + G1_AH);
                ldsm_x4(al[mt], ad + G1_AL);
            }
            unsigned bh[5][2], bl[5][2];
#pragma unroll
            for (int nt = 0; nt < 5; nt++) {
                const int row = wn + nt * 8 + (lane & 7);
                const int col = ks * 16 + ((lane >> 3) & 1) * 8;
                const unsigned bd = base + 80u * row + 2u * col;
                ldsm_x2(bh[nt], bd + G1_BH);
                ldsm_x2(bl[nt], bd + G1_BL);
            }
#pragma unroll
            for (int mt = 0; mt < 2; mt++)
#pragma unroll
                for (int nt = 0; nt < 5; nt++) {
                    mma_bf16(acc[mt][nt], ah[mt], bh[nt]);
                    mma_bf16(acc[mt][nt], ah[mt], bl[nt]);
                    mma_bf16(acc[mt][nt], al[mt], bh[nt]);
                }
        }
    };

    load_regs(0);
    store_smem(0);
    __syncthreads();
    for (int it = 0; it < 64; it++) {
        if (it + 1 < 64) load_regs((it + 1) * 32);
        compute(it & 1);
        if (it + 1 < 64) {
            __syncthreads();
            store_smem((it + 1) & 1);
            __syncthreads();
        }
    }

    // epilogue
#pragma unroll
    for (int mt = 0; mt < 2; mt++) {
#pragma unroll
        for (int nt = 0; nt < 5; nt++) {
            const int cb = wn + nt * 8 + 2 * (lane & 3);
            const int mA = m0 + wm + mt * 16 + (lane >> 2);
            const float* c = acc[mt][nt];
            if (cb < RNK) {
                unsigned h, l;
                split2(c[0], c[1], h, l);
                *(unsigned*)(g_dth + (size_t)mA * RNK + cb) = h;
                *(unsigned*)(g_dtl + (size_t)mA * RNK + cb) = l;
                split2(c[2], c[3], h, l);
                *(unsigned*)(g_dth + (size_t)(mA + 8) * RNK + cb) = h;
                *(unsigned*)(g_dtl + (size_t)(mA + 8) * RNK + cb) = l;
            } else if (cb < RNK + NST) {
                *(float2*)(g_B + (size_t)mA * NST + (cb - RNK)) = make_float2(c[0], c[1]);
                *(float2*)(g_B + (size_t)(mA + 8) * NST + (cb - RNK)) = make_float2(c[2], c[3]);
            } else {
                *(float2*)(g_C + (size_t)mA * NST + (cb - RNK - NST)) = make_float2(c[0], c[1]);
                *(float2*)(g_C + (size_t)(mA + 8) * NST + (cb - RNK - NST)) = make_float2(c[2], c[3]);
            }
        }
    }
}

// ---------------------------------------------------------------------------
// GEMM2 (mma.sync bf16 split): delta[M=16384, N=2048] =
//   softplus(dt[M,128] Wd[N,128]^T + bias). Block tile M=64, N=128, K=128
// single-shot. 8 warps = 2m x 4n, warp tile 32 x 32.
// smem: Ah/Al 64x136 bf16 (17408B each), Bh/Bl 128x136 (34816B each).
// ---------------------------------------------------------------------------
#define G2_AH 0
#define G2_AL 17408
#define G2_BH 34816
#define G2_BL 69632
#define G2_SMEM 104448

__global__ __launch_bounds__(256, 2) void gemm2_kernel(const float* __restrict__ bias)
{
    extern __shared__ __align__(16) char smem[];
    const unsigned sb = smem_u32(smem);
    const int tid = threadIdx.x, lane = tid & 31, w = tid >> 5;
    const int mt_ = blockIdx.x >> 4;
    const int nt_ = blockIdx.x & 15;
    const int m0 = mt_ * 64, d0 = nt_ * 128;
    const int wm = (w & 1) * 32;
    const int wn = (w >> 1) * 32;

    // load A: 2 planes x 1024 uint4
#pragma unroll
    for (int q = 0; q < 8; q++) {
        const int id = q * 256 + tid;
        const __nv_bfloat16* src = (id < 1024) ? g_dth : g_dtl;
        const int off = (id < 1024) ? G2_AH : G2_AL;
        const int rid = id & 1023;
        const int r = rid >> 4, c16 = rid & 15;
        uint4 v = *(const uint4*)(src + (size_t)(m0 + r) * RNK + c16 * 8);
        *(uint4*)(smem + off + 272 * r + 16 * c16) = v;
    }
    // load B: 2 planes x 2048 uint4
#pragma unroll
    for (int q = 0; q < 16; q++) {
        const int id = q * 256 + tid;
        const __nv_bfloat16* src = (id < 2048) ? g_wdh : g_wdl;
        const int off = (id < 2048) ? G2_BH : G2_BL;
        const int rid = id & 2047;
        const int r = rid >> 4, c16 = rid & 15;
        uint4 v = *(const uint4*)(src + (size_t)(d0 + r) * RNK + c16 * 8);
        *(uint4*)(smem + off + 272 * r + 16 * c16) = v;
    }
    __syncthreads();

    float acc[2][4][4];
#pragma unroll
    for (int i = 0; i < 2; i++)
#pragma unroll
        for (int j = 0; j < 4; j++)
#pragma unroll
            for (int q = 0; q < 4; q++) acc[i][j][q] = 0.f;

#pragma unroll
    for (int ks = 0; ks < 8; ks++) {
        const int kc = ks * 16 + ((lane >> 4) & 1) * 8;
        unsigned ah[2][4], al[2][4];
#pragma unroll
        for (int mt = 0; mt < 2; mt++) {
            const int row = wm + mt * 16 + (lane & 15);
            const unsigned ad = sb + 272u * row + 2u * kc;
            ldsm_x4(ah[mt], ad + G2_AH);
            ldsm_x4(al[mt], ad + G2_AL);
        }
        unsigned bh[4][2], bl[4][2];
#pragma unroll
        for (int nt = 0; nt < 4; nt++) {
            const int row = wn + nt * 8 + (lane & 7);
            const int col = ks * 16 + ((lane >> 3) & 1) * 8;
            const unsigned bd = sb + 272u * row + 2u * col;
            ldsm_x2(bh[nt], bd + G2_BH);
            ldsm_x2(bl[nt], bd + G2_BL);
        }
#pragma unroll
        for (int mt = 0; mt < 2; mt++)
#pragma unroll
            for (int nt = 0; nt < 4; nt++) {
                mma_bf16(acc[mt][nt], ah[mt], bh[nt]);
                mma_bf16(acc[mt][nt], ah[mt], bl[nt]);
                mma_bf16(acc[mt][nt], al[mt], bh[nt]);
            }
    }

    // epilogue: bias + softplus -> g_delta
#pragma unroll
    for (int mt = 0; mt < 2; mt++) {
#pragma unroll
        for (int nt = 0; nt < 4; nt++) {
            const int d = d0 + wn + nt * 8 + 2 * (lane & 3);
            const int mA = m0 + wm + mt * 16 + (lane >> 2);
            const float b0v = bias[d], b1v = bias[d + 1];
            const float* c = acc[mt][nt];
            float z0 = c[0] + b0v, z1 = c[1] + b1v;
            float z2 = c[2] + b0v, z3 = c[3] + b1v;
            z0 = (z0 > 20.f) ? z0 : log1pf(__expf(z0));
            z1 = (z1 > 20.f) ? z1 : log1pf(__expf(z1));
            z2 = (z2 > 20.f) ? z2 : log1pf(__expf(z2));
            z3 = (z3 > 20.f) ? z3 : log1pf(__expf(z3));
            *(float2*)(g_delta + (size_t)mA * DIN + d) = make_float2(z0, z1);
            *(float2*)(g_delta + (size_t)(mA + 8) * DIN + d) = make_float2(z2, z3);
        }
    }
}

// ---------------------------------------------------------------------------
// Segmented scan (unchanged from round 5)
// ---------------------------------------------------------------------------
__global__ __launch_bounds__(256) void scan_seg1_kernel(
    const float* __restrict__ x, const float* __restrict__ A_log)
{
    __shared__ __align__(16) float xs [SCH][64];
    __shared__ __align__(16) float dsm[SCH][64];
    __shared__ __align__(16) float Bs [SCH][16];

    const int tid  = threadIdx.x;
    const int ch   = tid >> 2;
    const int ng   = tid & 3;
    const int dg   = blockIdx.x & 31;
    const int bseg = blockIdx.x >> 5;
    const int b    = bseg >> 4;
    const int seg  = bseg & 15;
    const int d0   = dg << 6;
    const int d    = d0 + ch;

    const float4 al = *(const float4*)(A_log + (size_t)d * NST + 4 * ng);
    const float A0 = -__expf(al.x);
    const float A1 = -__expf(al.y);
    const float A2 = -__expf(al.z);
    const float A3 = -__expf(al.w);

    bool ok = (fabsf(A1 - A0 + 1.f) < 2e-3f) &&
              (fabsf(A2 - A1 + 1.f) < 2e-3f) &&
              (fabsf(A3 - A2 + 1.f) < 2e-3f);
    const unsigned fast = __all_sync(0xffffffffu, ok);

    const size_t t0 = (size_t)b * LEN + (size_t)seg * SEGLEN;
    const float* xg  = x       + t0 * DIN + d0;
    const float* dgp = g_delta + t0 * DIN + d0;
    const float* Bg  = g_B     + t0 * NST;

    const int rA = tid >> 4;
    const int qA = (tid & 15) * 4;
    const int rB = (tid & 63) >> 2;
    const int qB = (tid & 3) * 4;

    float h0 = 0.f, h1 = 0.f, h2 = 0.f, h3 = 0.f;
    float p0 = 1.f, p1 = 1.f, p2 = 1.f, p3 = 1.f;
    float4 px, pd, pb;

    px = *(const float4*)(xg + (size_t)rA * DIN + qA);
    pd = *(const float4*)(dgp + (size_t)rA * DIN + qA);
    if (tid < 64) pb = *(const float4*)(Bg + (size_t)rB * NST + qB);

    *(float4*)&xs [rA][qA] = px;
    *(float4*)&dsm[rA][qA] = pd;
    if (tid < 64) *(float4*)&Bs[rB][qB] = pb;
    __syncthreads();

    for (int c = 0; c < NCHS; c++) {
        if (c + 1 < NCHS) {
            const size_t off = (size_t)(c + 1) * SCH;
            px = *(const float4*)(xg + (off + rA) * DIN + qA);
            pd = *(const float4*)(dgp + (off + rA) * DIN + qA);
            if (tid < 64) pb = *(const float4*)(Bg + (off + rB) * NST + qB);
        }
        if (fast) {
#pragma unroll
            for (int j = 0; j < SCH; j++) {
                const float xv = xs [j][ch];
                const float dv = dsm[j][ch];
                const float4 Bv = *(const float4*)&Bs[j][4 * ng];
                const float e0 = __expf(dv * A0);
                const float r  = __expf(-dv);
                const float r2 = r * r;
                const float e1 = e0 * r, e2 = e0 * r2, e3 = e1 * r2;
                const float s = dv * xv;
                h0 = fmaf(e0, h0, s * Bv.x);
                h1 = fmaf(e1, h1, s * Bv.y);
                h2 = fmaf(e2, h2, s * Bv.z);
                h3 = fmaf(e3, h3, s * Bv.w);
                p0 *= e0; p1 *= e1; p2 *= e2; p3 *= e3;
            }
        } else {
#pragma unroll
            for (int j = 0; j < SCH; j++) {
                const float xv = xs [j][ch];
                const float dv = dsm[j][ch];
                const float4 Bv = *(const float4*)&Bs[j][4 * ng];
                const float e0 = __expf(dv * A0);
                const float e1 = __expf(dv * A1);
                const float e2 = __expf(dv * A2);
                const float e3 = __expf(dv * A3);
                const float s = dv * xv;
                h0 = fmaf(e0, h0, s * Bv.x);
                h1 = fmaf(e1, h1, s * Bv.y);
                h2 = fmaf(e2, h2, s * Bv.z);
                h3 = fmaf(e3, h3, s * Bv.w);
                p0 *= e0; p1 *= e1; p2 *= e2; p3 *= e3;
            }
        }
        __syncthreads();
        if (c + 1 < NCHS) {
            *(float4*)&xs [rA][qA] = px;
            *(float4*)&dsm[rA][qA] = pd;
            if (tid < 64) *(float4*)&Bs[rB][qB] = pb;
        }
        __syncthreads();
    }

    const size_t hb = (((size_t)(b * P_SEG + seg) * DIN) + d) * NST + 4 * ng;
    *(float4*)(g_hseg + hb) = make_float4(h0, h1, h2, h3);
    *(float4*)(g_pseg + hb) = make_float4(p0, p1, p2, p3);
}

__global__ __launch_bounds__(256) void scan_comb_kernel()
{
    const int tid  = threadIdx.x;
    const int cidx = blockIdx.x * 64 + (tid >> 2);
    const int ng   = tid & 3;
    const int b    = cidx >> 11;
    const int d    = cidx & (DIN - 1);

    float4 h = make_float4(0.f, 0.f, 0.f, 0.f);
#pragma unroll
    for (int s = 0; s < P_SEG; s++) {
        const size_t idx = (((size_t)(b * P_SEG + s) * DIN) + d) * NST + 4 * ng;
        *(float4*)(g_hin + idx) = h;
        const float4 Pv = *(const float4*)(g_pseg + idx);
        const float4 Lv = *(const float4*)(g_hseg + idx);
        h.x = fmaf(Pv.x, h.x, Lv.x);
        h.y = fmaf(Pv.y, h.y, Lv.y);
        h.z = fmaf(Pv.z, h.z, Lv.z);
        h.w = fmaf(Pv.w, h.w, Lv.w);
    }
}

__global__ __launch_bounds__(256) void scan_seg2_kernel(
    const float* __restrict__ x, const float* __restrict__ A_log,
    const float* __restrict__ Dpar, float* __restrict__ out)
{
    __shared__ __align__(16) float xs [SCH][64];
    __shared__ __align__(16) float dsm[SCH][64];
    __shared__ __align__(16) float ys [SCH][64];
    __shared__ __align__(16) float Bs [SCH][16];
    __shared__ __align__(16) float Cs [SCH][16];

    const int tid  = threadIdx.x;
    const int ch   = tid >> 2;
    const int ng   = tid & 3;
    const int dg   = blockIdx.x & 31;
    const int bseg = blockIdx.x >> 5;
    const int b    = bseg >> 4;
    const int seg  = bseg & 15;
    const int d0   = dg << 6;
    const int d    = d0 + ch;

    const float4 al = *(const float4*)(A_log + (size_t)d * NST + 4 * ng);
    const float A0 = -__expf(al.x);
    const float A1 = -__expf(al.y);
    const float A2 = -__expf(al.z);
    const float A3 = -__expf(al.w);
    const float Dd = Dpar[d];

    bool ok = (fabsf(A1 - A0 + 1.f) < 2e-3f) &&
              (fabsf(A2 - A1 + 1.f) < 2e-3f) &&
              (fabsf(A3 - A2 + 1.f) < 2e-3f);
    const unsigned fast = __all_sync(0xffffffffu, ok);

    const size_t t0 = (size_t)b * LEN + (size_t)seg * SEGLEN;
    const float* xg  = x       + t0 * DIN + d0;
    const float* dgp = g_delta + t0 * DIN + d0;
    const float* Bg  = g_B     + t0 * NST;
    const float* Cg  = g_C     + t0 * NST;
    float*       og  = out     + t0 * DIN + d0;

    const int rA = tid >> 4;
    const int qA = (tid & 15) * 4;
    const int rB = (tid & 63) >> 2;
    const int qB = (tid & 3) * 4;

    const size_t hb = (((size_t)(b * P_SEG + seg) * DIN) + d) * NST + 4 * ng;
    const float4 h_in = *(const float4*)(g_hin + hb);
    float h0 = h_in.x, h1 = h_in.y, h2 = h_in.z, h3 = h_in.w;

    float4 px, pd, pbc;

    px = *(const float4*)(xg + (size_t)rA * DIN + qA);
    pd = *(const float4*)(dgp + (size_t)rA * DIN + qA);
    if (tid < 64)       pbc = *(const float4*)(Bg + (size_t)rB * NST + qB);
    else if (tid < 128) pbc = *(const float4*)(Cg + (size_t)rB * NST + qB);

    *(float4*)&xs [rA][qA] = px;
    *(float4*)&dsm[rA][qA] = pd;
    if (tid < 64)       *(float4*)&Bs[rB][qB] = pbc;
    else if (tid < 128) *(float4*)&Cs[rB][qB] = pbc;
    __syncthreads();

    for (int c = 0; c < NCHS; c++) {
        if (c + 1 < NCHS) {
            const size_t off = (size_t)(c + 1) * SCH;
            px = *(const float4*)(xg + (off + rA) * DIN + qA);
            pd = *(const float4*)(dgp + (off + rA) * DIN + qA);
            if (tid < 64)       pbc = *(const float4*)(Bg + (off + rB) * NST + qB);
            else if (tid < 128) pbc = *(const float4*)(Cg + (off + rB) * NST + qB);
        }
        if (fast) {
#pragma unroll
            for (int j = 0; j < SCH; j++) {
                const float xv = xs [j][ch];
                const float dv = dsm[j][ch];
                const float4 Bv = *(const float4*)&Bs[j][4 * ng];
                const float4 Cv = *(const float4*)&Cs[j][4 * ng];
                const float e0 = __expf(dv * A0);
                const float r  = __expf(-dv);
                const float r2 = r * r;
                const float e1 = e0 * r, e2 = e0 * r2, e3 = e1 * r2;
                const float s = dv * xv;
                h0 = fmaf(e0, h0, s * Bv.x);
                h1 = fmaf(e1, h1, s * Bv.y);
                h2 = fmaf(e2, h2, s * Bv.z);
                h3 = fmaf(e3, h3, s * Bv.w);
                float y = h0 * Cv.x;
                y = fmaf(h1, Cv.y, y);
                y = fmaf(h2, Cv.z, y);
                y = fmaf(h3, Cv.w, y);
                y += __shfl_xor_sync(0xffffffffu, y, 1);
                y += __shfl_xor_sync(0xffffffffu, y, 2);
                if (ng == 0) ys[j][ch] = fmaf(Dd, xv, y);
            }
        } else {
#pragma unroll
            for (int j = 0; j < SCH; j++) {
                const float xv = xs [j][ch];
                const float dv = dsm[j][ch];
                const float4 Bv = *(const float4*)&Bs[j][4 * ng];
                const float4 Cv = *(const float4*)&Cs[j][4 * ng];
                const float e0 = __expf(dv * A0);
                const float e1 = __expf(dv * A1);
                const float e2 = __expf(dv * A2);
                const float e3 = __expf(dv * A3);
                const float s = dv * xv;
                h0 = fmaf(e0, h0, s * Bv.x);
                h1 = fmaf(e1, h1, s * Bv.y);
                h2 = fmaf(e2, h2, s * Bv.z);
                h3 = fmaf(e3, h3, s * Bv.w);
                float y = h0 * Cv.x;
                y = fmaf(h1, Cv.y, y);
                y = fmaf(h2, Cv.z, y);
                y = fmaf(h3, Cv.w, y);
                y += __shfl_xor_sync(0xffffffffu, y, 1);
                y += __shfl_xor_sync(0xffffffffu, y, 2);
                if (ng == 0) ys[j][ch] = fmaf(Dd, xv, y);
            }
        }
        __syncthreads();
        {
            const size_t off = (size_t)c * SCH;
            *(float4*)(og + (off + rA) * DIN + qA) = *(const float4*)&ys[rA][qA];
        }
        if (c + 1 < NCHS) {
            *(float4*)&xs [rA][qA] = px;
            *(float4*)&dsm[rA][qA] = pd;
            if (tid < 64)       *(float4*)&Bs[rB][qB] = pbc;
            else if (tid < 128) *(float4*)&Cs[rB][qB] = pbc;
        }
        __syncthreads();
    }
}

// ---------------------------------------------------------------------------
// Launch
// ---------------------------------------------------------------------------
extern "C" void kernel_launch(void* const* d_in, const int* in_sizes, int n_in,
                              void* d_out, int out_size)
{
    const float* x         = (const float*)d_in[0];
    const float* A_log     = (const float*)d_in[1];
    const float* D_param   = (const float*)d_in[2];
    const float* x_proj_w  = (const float*)d_in[3];
    const float* dt_proj_w = (const float*)d_in[4];
    const float* dt_proj_b = (const float*)d_in[5];
    float* out = (float*)d_out;

    cudaFuncSetAttribute(gemm1_kernel, cudaFuncAttributeMaxDynamicSharedMemorySize, G1_SMEM);
    cudaFuncSetAttribute(gemm2_kernel, cudaFuncAttributeMaxDynamicSharedMemorySize, G2_SMEM);

    prep_kernel<<<576, 256>>>(x_proj_w, dt_proj_w);
    gemm1_kernel<<<M_TOT / 64, 256, G1_SMEM>>>(x);
    gemm2_kernel<<<(M_TOT / 64) * (DIN / 128), 256, G2_SMEM>>>(dt_proj_b);
    scan_seg1_kernel<<<BATCH * P_SEG * (DIN / 64), 256>>>(x, A_log);
    scan_comb_kernel<<<BATCH * DIN / 64, 256>>>();
    scan_seg2_kernel<<<BATCH * P_SEG * (DIN / 64), 256>>>(x, A_log, D_param, out);
}

// round 9
// speedup vs baseline: 2.7394x; 1.3083x over previous
#include <cuda_runtime.h>
#include <cuda_bf16.h>
#include <math.h>
#include <stdint.h>

#define BATCH 4
#define LEN   4096
#define DIN   2048
#define NST   16
#define RNK   128
#define M_TOT (BATCH*LEN)   // 16384
#define SCH   16
#define P_SEG 16
#define SEGLEN (LEN/P_SEG)  // 256
#define NCHS  (SEGLEN/SCH)  // 16
#define CPB   128           // channels (=threads) per scan block

// ---------------------------------------------------------------------------
// Device scratch
// ---------------------------------------------------------------------------
__device__ float g_B [(size_t)M_TOT * NST];
__device__ float g_C [(size_t)M_TOT * NST];
__device__ float g_delta[(size_t)M_TOT * DIN];
__device__ float g_hseg[(size_t)BATCH * P_SEG * DIN * NST];
__device__ float g_pseg[(size_t)BATCH * P_SEG * DIN * NST];
__device__ float g_hin [(size_t)BATCH * P_SEG * DIN * NST];
// bf16 hi/lo split operands (row-major, k contiguous)
__device__ __nv_bfloat16 g_w1h[(size_t)160 * DIN];
__device__ __nv_bfloat16 g_w1l[(size_t)160 * DIN];
__device__ __nv_bfloat16 g_wdh[(size_t)DIN * RNK];
__device__ __nv_bfloat16 g_wdl[(size_t)DIN * RNK];
__device__ __nv_bfloat16 g_dth[(size_t)M_TOT * RNK];
__device__ __nv_bfloat16 g_dtl[(size_t)M_TOT * RNK];

// ---------------------------------------------------------------------------
// helpers
// ---------------------------------------------------------------------------
__device__ __forceinline__ unsigned smem_u32(const void* p) {
    unsigned a;
    asm("{ .reg .u64 t; cvta.to.shared.u64 t, %1; cvt.u32.u64 %0, t; }"
        : "=r"(a) : "l"(p));
    return a;
}
__device__ __forceinline__ void split2(float a, float b, unsigned& h, unsigned& l) {
    __nv_bfloat16 ha = __float2bfloat16(a), hb = __float2bfloat16(b);
    float ra = a - __bfloat162float(ha), rb = b - __bfloat162float(hb);
    __nv_bfloat16 la = __float2bfloat16(ra), lb = __float2bfloat16(rb);
    h = (unsigned)__bfloat16_as_ushort(ha) | ((unsigned)__bfloat16_as_ushort(hb) << 16);
    l = (unsigned)__bfloat16_as_ushort(la) | ((unsigned)__bfloat16_as_ushort(lb) << 16);
}
__device__ __forceinline__ void splitf4(float4 v, uint2& h, uint2& l) {
    split2(v.x, v.y, h.x, l.x);
    split2(v.z, v.w, h.y, l.y);
}
__device__ __forceinline__ void ldsm_x4(unsigned* a, unsigned addr) {
    asm volatile("ldmatrix.sync.aligned.m8n8.x4.shared.b16 {%0,%1,%2,%3}, [%4];"
        : "=r"(a[0]), "=r"(a[1]), "=r"(a[2]), "=r"(a[3]) : "r"(addr));
}
__device__ __forceinline__ void ldsm_x2(unsigned* a, unsigned addr) {
    asm volatile("ldmatrix.sync.aligned.m8n8.x2.shared.b16 {%0,%1}, [%2];"
        : "=r"(a[0]), "=r"(a[1]) : "r"(addr));
}
__device__ __forceinline__ void mma_bf16(float* c, const unsigned* a, const unsigned* b) {
    asm volatile(
        "mma.sync.aligned.m16n8k16.row.col.f32.bf16.bf16.f32 "
        "{%0,%1,%2,%3},{%4,%5,%6,%7},{%8,%9},{%0,%1,%2,%3};"
        : "+f"(c[0]), "+f"(c[1]), "+f"(c[2]), "+f"(c[3])
        : "r"(a[0]), "r"(a[1]), "r"(a[2]), "r"(a[3]), "r"(b[0]), "r"(b[1]));
}
// e[k] = r^(k+1), k=0..15, depth-4 mul tree
__device__ __forceinline__ void pow16(float r, float* e) {
    e[0] = r;
    e[1] = r * r;
    e[2] = e[1] * r;
    e[3] = e[1] * e[1];
    e[4] = e[3] * r;
    e[5] = e[3] * e[1];
    e[6] = e[3] * e[2];
    e[7] = e[3] * e[3];
    e[8]  = e[7] * r;
    e[9]  = e[7] * e[1];
    e[10] = e[7] * e[2];
    e[11] = e[7] * e[3];
    e[12] = e[7] * e[4];
    e[13] = e[7] * e[5];
    e[14] = e[7] * e[6];
    e[15] = e[7] * e[7];
}

// ---------------------------------------------------------------------------
// PREP (unchanged)
// ---------------------------------------------------------------------------
__global__ __launch_bounds__(256) void prep_kernel(
    const float* __restrict__ W1, const float* __restrict__ Wd)
{
    const int id = blockIdx.x * 256 + threadIdx.x;
    if (id < 81920) {
        const int r = id >> 9, c4 = id & 511;
        float4 v = *(const float4*)(W1 + (size_t)r * DIN + c4 * 4);
        uint2 h, l; splitf4(v, h, l);
        *(uint2*)(g_w1h + (size_t)r * DIN + c4 * 4) = h;
        *(uint2*)(g_w1l + (size_t)r * DIN + c4 * 4) = l;
    } else {
        const int id2 = id - 81920;
        const int r = id2 >> 5, c4 = id2 & 31;
        float4 v = *(const float4*)(Wd + (size_t)r * RNK + c4 * 4);
        uint2 h, l; splitf4(v, h, l);
        *(uint2*)(g_wdh + (size_t)r * RNK + c4 * 4) = h;
        *(uint2*)(g_wdl + (size_t)r * RNK + c4 * 4) = l;
    }
}

// ---------------------------------------------------------------------------
// GEMM1 (unchanged from round 7)
// ---------------------------------------------------------------------------
#define G1_AH 0
#define G1_AL 5120
#define G1_BH 10240
#define G1_BL 23040
#define G1_BUF 35840
#define G1_SMEM (2*G1_BUF)

__global__ __launch_bounds__(256, 2) void gemm1_kernel(const float* __restrict__ X)
{
    extern __shared__ __align__(16) char smem[];
    const unsigned sb = smem_u32(smem);
    const int tid = threadIdx.x, lane = tid & 31, w = tid >> 5;
    const int m0 = blockIdx.x * 64;
    const int wm = (w & 1) * 32;
    const int wn = (w >> 1) * 40;

    float acc[2][5][4];
#pragma unroll
    for (int i = 0; i < 2; i++)
#pragma unroll
        for (int j = 0; j < 5; j++)
#pragma unroll
            for (int q = 0; q < 4; q++) acc[i][j][q] = 0.f;

    const int rX0 = tid >> 3, cX0 = (tid & 7) * 4;
    const int rX1 = (tid + 256) >> 3, cX1 = cX0;

    float4 xr[2]; uint4 wr[5];

    auto load_regs = [&](int k0) {
        xr[0] = *(const float4*)(X + (size_t)(m0 + rX0) * DIN + k0 + cX0);
        xr[1] = *(const float4*)(X + (size_t)(m0 + rX1) * DIN + k0 + cX1);
#pragma unroll
        for (int q = 0; q < 5; q++) {
            const int id = q * 256 + tid;
            const __nv_bfloat16* src = (id < 640) ? g_w1h : g_w1l;
            const int rid = (id < 640) ? id : id - 640;
            const int r = rid >> 2, c16 = rid & 3;
            wr[q] = *(const uint4*)(src + (size_t)r * DIN + k0 + c16 * 8);
        }
    };
    auto store_smem = [&](int bi) {
        char* buf = smem + bi * G1_BUF;
        {
            uint2 h, l; splitf4(xr[0], h, l);
            *(uint2*)(buf + G1_AH + 80 * rX0 + 2 * cX0) = h;
            *(uint2*)(buf + G1_AL + 80 * rX0 + 2 * cX0) = l;
            splitf4(xr[1], h, l);
            *(uint2*)(buf + G1_AH + 80 * rX1 + 2 * cX1) = h;
            *(uint2*)(buf + G1_AL + 80 * rX1 + 2 * cX1) = l;
        }
#pragma unroll
        for (int q = 0; q < 5; q++) {
            const int id = q * 256 + tid;
            const int off = (id < 640) ? G1_BH : G1_BL;
            const int rid = (id < 640) ? id : id - 640;
            const int r = rid >> 2, c16 = rid & 3;
            *(uint4*)(buf + off + 80 * r + 16 * c16) = wr[q];
        }
    };
    auto compute = [&](int bi) {
        const unsigned base = sb + bi * G1_BUF;
#pragma unroll
        for (int ks = 0; ks < 2; ks++) {
            const int kc = ks * 16 + ((lane >> 4) & 1) * 8;
            unsigned ah[2][4], al[2][4];
#pragma unroll
            for (int mt = 0; mt < 2; mt++) {
                const int row = wm + mt * 16 + (lane & 15);
                const unsigned ad = base + 80u * row + 2u * kc;
                ldsm_x4(ah[mt], ad + G1_AH);
                ldsm_x4(al[mt], ad + G1_AL);
            }
            unsigned bh[5][2], bl[5][2];
#pragma unroll
            for (int nt = 0; nt < 5; nt++) {
                const int row = wn + nt * 8 + (lane & 7);
                const int col = ks * 16 + ((lane >> 3) & 1) * 8;
                const unsigned bd = base + 80u * row + 2u * col;
                ldsm_x2(bh[nt], bd + G1_BH);
                ldsm_x2(bl[nt], bd + G1_BL);
            }
#pragma unroll
            for (int mt = 0; mt < 2; mt++)
#pragma unroll
                for (int nt = 0; nt < 5; nt++) {
                    mma_bf16(acc[mt][nt], ah[mt], bh[nt]);
                    mma_bf16(acc[mt][nt], ah[mt], bl[nt]);
                    mma_bf16(acc[mt][nt], al[mt], bh[nt]);
                }
        }
    };

    load_regs(0);
    store_smem(0);
    __syncthreads();
    for (int it = 0; it < 64; it++) {
        if (it + 1 < 64) load_regs((it + 1) * 32);
        compute(it & 1);
        if (it + 1 < 64) {
            __syncthreads();
            store_smem((it + 1) & 1);
            __syncthreads();
        }
    }

#pragma unroll
    for (int mt = 0; mt < 2; mt++) {
#pragma unroll
        for (int nt = 0; nt < 5; nt++) {
            const int cb = wn + nt * 8 + 2 * (lane & 3);
            const int mA = m0 + wm + mt * 16 + (lane >> 2);
            const float* c = acc[mt][nt];
            if (cb < RNK) {
                unsigned h, l;
                split2(c[0], c[1], h, l);
                *(unsigned*)(g_dth + (size_t)mA * RNK + cb) = h;
                *(unsigned*)(g_dtl + (size_t)mA * RNK + cb) = l;
                split2(c[2], c[3], h, l);
                *(unsigned*)(g_dth + (size_t)(mA + 8) * RNK + cb) = h;
                *(unsigned*)(g_dtl + (size_t)(mA + 8) * RNK + cb) = l;
            } else if (cb < RNK + NST) {
                *(float2*)(g_B + (size_t)mA * NST + (cb - RNK)) = make_float2(c[0], c[1]);
                *(float2*)(g_B + (size_t)(mA + 8) * NST + (cb - RNK)) = make_float2(c[2], c[3]);
            } else {
                *(float2*)(g_C + (size_t)mA * NST + (cb - RNK - NST)) = make_float2(c[0], c[1]);
                *(float2*)(g_C + (size_t)(mA + 8) * NST + (cb - RNK - NST)) = make_float2(c[2], c[3]);
            }
        }
    }
}

// ---------------------------------------------------------------------------
// GEMM2 (unchanged from round 7)
// ---------------------------------------------------------------------------
#define G2_AH 0
#define G2_AL 17408
#define G2_BH 34816
#define G2_BL 69632
#define G2_SMEM 104448

__global__ __launch_bounds__(256, 2) void gemm2_kernel(const float* __restrict__ bias)
{
    extern __shared__ __align__(16) char smem[];
    const unsigned sb = smem_u32(smem);
    const int tid = threadIdx.x, lane = tid & 31, w = tid >> 5;
    const int mt_ = blockIdx.x >> 4;
    const int nt_ = blockIdx.x & 15;
    const int m0 = mt_ * 64, d0 = nt_ * 128;
    const int wm = (w & 1) * 32;
    const int wn = (w >> 1) * 32;

#pragma unroll
    for (int q = 0; q < 8; q++) {
        const int id = q * 256 + tid;
        const __nv_bfloat16* src = (id < 1024) ? g_dth : g_dtl;
        const int off = (id < 1024) ? G2_AH : G2_AL;
        const int rid = id & 1023;
        const int r = rid >> 4, c16 = rid & 15;
        uint4 v = *(const uint4*)(src + (size_t)(m0 + r) * RNK + c16 * 8);
        *(uint4*)(smem + off + 272 * r + 16 * c16) = v;
    }
#pragma unroll
    for (int q = 0; q < 16; q++) {
        const int id = q * 256 + tid;
        const __nv_bfloat16* src = (id < 2048) ? g_wdh : g_wdl;
        const int off = (id < 2048) ? G2_BH : G2_BL;
        const int rid = id & 2047;
        const int r = rid >> 4, c16 = rid & 15;
        uint4 v = *(const uint4*)(src + (size_t)(d0 + r) * RNK + c16 * 8);
        *(uint4*)(smem + off + 272 * r + 16 * c16) = v;
    }
    __syncthreads();

    float acc[2][4][4];
#pragma unroll
    for (int i = 0; i < 2; i++)
#pragma unroll
        for (int j = 0; j < 4; j++)
#pragma unroll
            for (int q = 0; q < 4; q++) acc[i][j][q] = 0.f;

#pragma unroll
    for (int ks = 0; ks < 8; ks++) {
        const int kc = ks * 16 + ((lane >> 4) & 1) * 8;
        unsigned ah[2][4], al[2][4];
#pragma unroll
        for (int mt = 0; mt < 2; mt++) {
            const int row = wm + mt * 16 + (lane & 15);
            const unsigned ad = sb + 272u * row + 2u * kc;
            ldsm_x4(ah[mt], ad + G2_AH);
            ldsm_x4(al[mt], ad + G2_AL);
        }
        unsigned bh[4][2], bl[4][2];
#pragma unroll
        for (int nt = 0; nt < 4; nt++) {
            const int row = wn + nt * 8 + (lane & 7);
            const int col = ks * 16 + ((lane >> 3) & 1) * 8;
            const unsigned bd = sb + 272u * row + 2u * col;
            ldsm_x2(bh[nt], bd + G2_BH);
            ldsm_x2(bl[nt], bd + G2_BL);
        }
#pragma unroll
        for (int mt = 0; mt < 2; mt++)
#pragma unroll
            for (int nt = 0; nt < 4; nt++) {
                mma_bf16(acc[mt][nt], ah[mt], bh[nt]);
                mma_bf16(acc[mt][nt], ah[mt], bl[nt]);
                mma_bf16(acc[mt][nt], al[mt], bh[nt]);
            }
    }

#pragma unroll
    for (int mt = 0; mt < 2; mt++) {
#pragma unroll
        for (int nt = 0; nt < 4; nt++) {
            const int d = d0 + wn + nt * 8 + 2 * (lane & 3);
            const int mA = m0 + wm + mt * 16 + (lane >> 2);
            const float b0v = bias[d], b1v = bias[d + 1];
            const float* c = acc[mt][nt];
            float z0 = c[0] + b0v, z1 = c[1] + b1v;
            float z2 = c[2] + b0v, z3 = c[3] + b1v;
            z0 = (z0 > 20.f) ? z0 : log1pf(__expf(z0));
            z1 = (z1 > 20.f) ? z1 : log1pf(__expf(z1));
            z2 = (z2 > 20.f) ? z2 : log1pf(__expf(z2));
            z3 = (z3 > 20.f) ? z3 : log1pf(__expf(z3));
            *(float2*)(g_delta + (size_t)mA * DIN + d) = make_float2(z0, z1);
            *(float2*)(g_delta + (size_t)(mA + 8) * DIN + d) = make_float2(z2, z3);
        }
    }
}

// ---------------------------------------------------------------------------
// Scan v5: 1 thread per channel, 16 states in registers.
// Fast path (A = -(1..16)): e_n = r^(n+1) with r = exp(-delta) -> ONE MUFU
// per channel-step + depth-4 mul tree. Decay products replaced by sum(delta).
// Block = 128 threads = 128 channels. grid = 4b x 16seg x 16dg = 1024.
// ---------------------------------------------------------------------------
__global__ __launch_bounds__(CPB) void scan_seg1_kernel(
    const float* __restrict__ x, const float* __restrict__ A_log)
{
    __shared__ __align__(16) float xs [SCH][CPB];
    __shared__ __align__(16) float dsm[SCH][CPB];
    __shared__ __align__(16) float Bs [SCH][16];

    const int tid  = threadIdx.x;
    const int dg   = blockIdx.x & 15;
    const int bseg = blockIdx.x >> 4;
    const int b    = bseg >> 4;
    const int seg  = bseg & 15;
    const int d    = dg * CPB + tid;

    float A[16];
#pragma unroll
    for (int q = 0; q < 4; q++) {
        float4 v = *(const float4*)(A_log + (size_t)d * NST + 4 * q);
        A[4*q+0] = -__expf(v.x); A[4*q+1] = -__expf(v.y);
        A[4*q+2] = -__expf(v.z); A[4*q+3] = -__expf(v.w);
    }
    bool ok = fabsf(A[0] + 1.f) < 2e-3f;
#pragma unroll
    for (int i = 1; i < 16; i++) ok = ok && (fabsf(A[i] - A[i-1] + 1.f) < 2e-3f);
    const unsigned fast = __all_sync(0xffffffffu, ok);

    const size_t t0 = (size_t)b * LEN + (size_t)seg * SEGLEN;
    const float* xg  = x       + t0 * DIN + dg * CPB;
    const float* dgp = g_delta + t0 * DIN + dg * CPB;
    const float* Bg  = g_B     + t0 * NST;

    const int rA = tid >> 5;              // base row (0..3), +4 per q
    const int qA = (tid & 31) * 4;
    const int rB = (tid & 63) >> 2;
    const int qB = (tid & 3) * 4;

    float h[16];
#pragma unroll
    for (int i = 0; i < 16; i++) h[i] = 0.f;
    float Sd = 0.f;

    float4 px[4], pd[4], pb;
#pragma unroll
    for (int q = 0; q < 4; q++) {
        px[q] = *(const float4*)(xg  + (size_t)(rA + 4 * q) * DIN + qA);
        pd[q] = *(const float4*)(dgp + (size_t)(rA + 4 * q) * DIN + qA);
    }
    if (tid < 64) pb = *(const float4*)(Bg + (size_t)rB * NST + qB);
#pragma unroll
    for (int q = 0; q < 4; q++) {
        *(float4*)&xs [rA + 4 * q][qA] = px[q];
        *(float4*)&dsm[rA + 4 * q][qA] = pd[q];
    }
    if (tid < 64) *(float4*)&Bs[rB][qB] = pb;
    __syncthreads();

    for (int c = 0; c < NCHS; c++) {
        if (c + 1 < NCHS) {
            const size_t off = (size_t)(c + 1) * SCH;
#pragma unroll
            for (int q = 0; q < 4; q++) {
                px[q] = *(const float4*)(xg  + (off + rA + 4 * q) * DIN + qA);
                pd[q] = *(const float4*)(dgp + (off + rA + 4 * q) * DIN + qA);
            }
            if (tid < 64) pb = *(const float4*)(Bg + (off + rB) * NST + qB);
        }

        if (fast) {
#pragma unroll
            for (int j = 0; j < SCH; j++) {
                const float dv = dsm[j][tid];
                const float xv = xs [j][tid];
                float Bv[16];
#pragma unroll
                for (int q = 0; q < 4; q++)
                    *(float4*)&Bv[4 * q] = *(const float4*)&Bs[j][4 * q];
                const float r = __expf(-dv);
                const float s = dv * xv;
                Sd += dv;
                float e[16]; pow16(r, e);
#pragma unroll
                for (int i = 0; i < 16; i++)
                    h[i] = fmaf(e[i], h[i], s * Bv[i]);
            }
        } else {
#pragma unroll
            for (int j = 0; j < SCH; j++) {
                const float dv = dsm[j][tid];
                const float xv = xs [j][tid];
                float Bv[16];
#pragma unroll
                for (int q = 0; q < 4; q++)
                    *(float4*)&Bv[4 * q] = *(const float4*)&Bs[j][4 * q];
                const float s = dv * xv;
                Sd += dv;
#pragma unroll
                for (int i = 0; i < 16; i++) {
                    const float e = __expf(dv * A[i]);
                    h[i] = fmaf(e, h[i], s * Bv[i]);
                }
            }
        }
        __syncthreads();
        if (c + 1 < NCHS) {
#pragma unroll
            for (int q = 0; q < 4; q++) {
                *(float4*)&xs [rA + 4 * q][qA] = px[q];
                *(float4*)&dsm[rA + 4 * q][qA] = pd[q];
            }
            if (tid < 64) *(float4*)&Bs[rB][qB] = pb;
        }
        __syncthreads();
    }

    float p[16];
    if (fast) {
        const float R = __expf(-Sd);
        pow16(R, p);
    } else {
#pragma unroll
        for (int i = 0; i < 16; i++) p[i] = __expf(A[i] * Sd);
    }
    const size_t hb = (((size_t)(b * P_SEG + seg) * DIN) + d) * NST;
#pragma unroll
    for (int q = 0; q < 4; q++) {
        *(float4*)(g_hseg + hb + 4 * q) = *(const float4*)&h[4 * q];
        *(float4*)(g_pseg + hb + 4 * q) = *(const float4*)&p[4 * q];
    }
}

__global__ __launch_bounds__(256) void scan_comb_kernel()
{
    const int tid  = threadIdx.x;
    const int cidx = blockIdx.x * 64 + (tid >> 2);
    const int ng   = tid & 3;
    const int b    = cidx >> 11;
    const int d    = cidx & (DIN - 1);

    float4 h = make_float4(0.f, 0.f, 0.f, 0.f);
#pragma unroll
    for (int s = 0; s < P_SEG; s++) {
        const size_t idx = (((size_t)(b * P_SEG + s) * DIN) + d) * NST + 4 * ng;
        *(float4*)(g_hin + idx) = h;
        const float4 Pv = *(const float4*)(g_pseg + idx);
        const float4 Lv = *(const float4*)(g_hseg + idx);
        h.x = fmaf(Pv.x, h.x, Lv.x);
        h.y = fmaf(Pv.y, h.y, Lv.y);
        h.z = fmaf(Pv.z, h.z, Lv.z);
        h.w = fmaf(Pv.w, h.w, Lv.w);
    }
}

__global__ __launch_bounds__(CPB) void scan_seg2_kernel(
    const float* __restrict__ x, const float* __restrict__ A_log,
    const float* __restrict__ Dpar, float* __restrict__ out)
{
    __shared__ __align__(16) float xs [SCH][CPB];
    __shared__ __align__(16) float dsm[SCH][CPB];
    __shared__ __align__(16) float ys [SCH][CPB];
    __shared__ __align__(16) float Bs [SCH][16];
    __shared__ __align__(16) float Cs [SCH][16];

    const int tid  = threadIdx.x;
    const int dg   = blockIdx.x & 15;
    const int bseg = blockIdx.x >> 4;
    const int b    = bseg >> 4;
    const int seg  = bseg & 15;
    const int d    = dg * CPB + tid;

    float A[16];
#pragma unroll
    for (int q = 0; q < 4; q++) {
        float4 v = *(const float4*)(A_log + (size_t)d * NST + 4 * q);
        A[4*q+0] = -__expf(v.x); A[4*q+1] = -__expf(v.y);
        A[4*q+2] = -__expf(v.z); A[4*q+3] = -__expf(v.w);
    }
    bool ok = fabsf(A[0] + 1.f) < 2e-3f;
#pragma unroll
    for (int i = 1; i < 16; i++) ok = ok && (fabsf(A[i] - A[i-1] + 1.f) < 2e-3f);
    const unsigned fast = __all_sync(0xffffffffu, ok);
    const float Dd = Dpar[d];

    const size_t t0 = (size_t)b * LEN + (size_t)seg * SEGLEN;
    const float* xg  = x       + t0 * DIN + dg * CPB;
    const float* dgp = g_delta + t0 * DIN + dg * CPB;
    const float* Bg  = g_B     + t0 * NST;
    const float* Cg  = g_C     + t0 * NST;
    float*       og  = out     + t0 * DIN + dg * CPB;

    const int rA = tid >> 5;
    const int qA = (tid & 31) * 4;
    const int rB = (tid & 63) >> 2;
    const int qB = (tid & 3) * 4;

    float h[16];
    const size_t hb = (((size_t)(b * P_SEG + seg) * DIN) + d) * NST;
#pragma unroll
    for (int q = 0; q < 4; q++)
        *(float4*)&h[4 * q] = *(const float4*)(g_hin + hb + 4 * q);

    float4 px[4], pd[4], pbc;
#pragma unroll
    for (int q = 0; q < 4; q++) {
        px[q] = *(const float4*)(xg  + (size_t)(rA + 4 * q) * DIN + qA);
        pd[q] = *(const float4*)(dgp + (size_t)(rA + 4 * q) * DIN + qA);
    }
    if (tid < 64)       pbc = *(const float4*)(Bg + (size_t)rB * NST + qB);
    else                pbc = *(const float4*)(Cg + (size_t)rB * NST + qB);
#pragma unroll
    for (int q = 0; q < 4; q++) {
        *(float4*)&xs [rA + 4 * q][qA] = px[q];
        *(float4*)&dsm[rA + 4 * q][qA] = pd[q];
    }
    if (tid < 64) *(float4*)&Bs[rB][qB] = pbc;
    else          *(float4*)&Cs[rB][qB] = pbc;
    __syncthreads();

    for (int c = 0; c < NCHS; c++) {
        if (c + 1 < NCHS) {
            const size_t off = (size_t)(c + 1) * SCH;
#pragma unroll
            for (int q = 0; q < 4; q++) {
                px[q] = *(const float4*)(xg  + (off + rA + 4 * q) * DIN + qA);
                pd[q] = *(const float4*)(dgp + (off + rA + 4 * q) * DIN + qA);
            }
            if (tid < 64) pbc = *(const float4*)(Bg + (off + rB) * NST + qB);
            else          pbc = *(const float4*)(Cg + (off + rB) * NST + qB);
        }

        if (fast) {
#pragma unroll
            for (int j = 0; j < SCH; j++) {
                const float dv = dsm[j][tid];
                const float xv = xs [j][tid];
                float Bv[16], Cv[16];
#pragma unroll
                for (int q = 0; q < 4; q++) {
                    *(float4*)&Bv[4 * q] = *(const float4*)&Bs[j][4 * q];
                    *(float4*)&Cv[4 * q] = *(const float4*)&Cs[j][4 * q];
                }
                const float r = __expf(-dv);
                const float s = dv * xv;
                float e[16]; pow16(r, e);
                float y = 0.f;
#pragma unroll
                for (int i = 0; i < 16; i++) {
                    h[i] = fmaf(e[i], h[i], s * Bv[i]);
                    y = fmaf(h[i], Cv[i], y);
                }
                ys[j][tid] = fmaf(Dd, xv, y);
            }
        } else {
#pragma unroll
            for (int j = 0; j < SCH; j++) {
                const float dv = dsm[j][tid];
                const float xv = xs [j][tid];
                float Bv[16], Cv[16];
#pragma unroll
                for (int q = 0; q < 4; q++) {
                    *(float4*)&Bv[4 * q] = *(const float4*)&Bs[j][4 * q];
                    *(float4*)&Cv[4 * q] = *(const float4*)&Cs[j][4 * q];
                }
                const float s = dv * xv;
                float y = 0.f;
#pragma unroll
                for (int i = 0; i < 16; i++) {
                    const float e = __expf(dv * A[i]);
                    h[i] = fmaf(e, h[i], s * Bv[i]);
                    y = fmaf(h[i], Cv[i], y);
                }
                ys[j][tid] = fmaf(Dd, xv, y);
            }
        }
        __syncthreads();
        {
            const size_t off = (size_t)c * SCH;
#pragma unroll
            for (int q = 0; q < 4; q++)
                *(float4*)(og + (off + rA + 4 * q) * DIN + qA) =
                    *(const float4*)&ys[rA + 4 * q][qA];
        }
        if (c + 1 < NCHS) {
#pragma unroll
            for (int q = 0; q < 4; q++) {
                *(float4*)&xs [rA + 4 * q][qA] = px[q];
                *(float4*)&dsm[rA + 4 * q][qA] = pd[q];
            }
            if (tid < 64) *(float4*)&Bs[rB][qB] = pbc;
            else          *(float4*)&Cs[rB][qB] = pbc;
        }
        __syncthreads();
    }
}

// ---------------------------------------------------------------------------
// Launch
// ---------------------------------------------------------------------------
extern "C" void kernel_launch(void* const* d_in, const int* in_sizes, int n_in,
                              void* d_out, int out_size)
{
    const float* x         = (const float*)d_in[0];
    const float* A_log     = (const float*)d_in[1];
    const float* D_param   = (const float*)d_in[2];
    const float* x_proj_w  = (const float*)d_in[3];
    const float* dt_proj_w = (const float*)d_in[4];
    const float* dt_proj_b = (const float*)d_in[5];
    float* out = (float*)d_out;

    cudaFuncSetAttribute(gemm1_kernel, cudaFuncAttributeMaxDynamicSharedMemorySize, G1_SMEM);
    cudaFuncSetAttribute(gemm2_kernel, cudaFuncAttributeMaxDynamicSharedMemorySize, G2_SMEM);

    prep_kernel<<<576, 256>>>(x_proj_w, dt_proj_w);
    gemm1_kernel<<<M_TOT / 64, 256, G1_SMEM>>>(x);
    gemm2_kernel<<<(M_TOT / 64) * (DIN / 128), 256, G2_SMEM>>>(dt_proj_b);
    scan_seg1_kernel<<<BATCH * P_SEG * (DIN / CPB), CPB>>>(x, A_log);
    scan_comb_kernel<<<BATCH * DIN / 64, 256>>>();
    scan_seg2_kernel<<<BATCH * P_SEG * (DIN / CPB), CPB>>>(x, A_log, D_param, out);
}

// round 10
// speedup vs baseline: 2.9446x; 1.0749x over previous
#include <cuda_runtime.h>
#include <cuda_bf16.h>
#include <math.h>
#include <stdint.h>

#define BATCH 4
#define LEN   4096
#define DIN   2048
#define NST   16
#define RNK   128
#define M_TOT (BATCH*LEN)   // 16384
#define SCH   16
#define P_SEG 16
#define SEGLEN (LEN/P_SEG)  // 256
#define NCHS  (SEGLEN/SCH)  // 16
#define CPB   128           // channels (=threads) per scan block

typedef unsigned long long u64;

// ---------------------------------------------------------------------------
// Device scratch
// ---------------------------------------------------------------------------
__device__ float g_B [(size_t)M_TOT * NST];
__device__ float g_C [(size_t)M_TOT * NST];
__device__ float g_delta[(size_t)M_TOT * DIN];
__device__ float g_hseg[(size_t)BATCH * P_SEG * DIN * NST];
__device__ float g_pseg[(size_t)BATCH * P_SEG * DIN * NST];
__device__ float g_hin [(size_t)BATCH * P_SEG * DIN * NST];
// bf16 hi/lo split operands (row-major, k contiguous)
__device__ __nv_bfloat16 g_w1h[(size_t)160 * DIN];
__device__ __nv_bfloat16 g_w1l[(size_t)160 * DIN];
__device__ __nv_bfloat16 g_wdh[(size_t)DIN * RNK];
__device__ __nv_bfloat16 g_wdl[(size_t)DIN * RNK];
__device__ __nv_bfloat16 g_dth[(size_t)M_TOT * RNK];
__device__ __nv_bfloat16 g_dtl[(size_t)M_TOT * RNK];

// ---------------------------------------------------------------------------
// helpers
// ---------------------------------------------------------------------------
__device__ __forceinline__ unsigned smem_u32(const void* p) {
    unsigned a;
    asm("{ .reg .u64 t; cvta.to.shared.u64 t, %1; cvt.u32.u64 %0, t; }"
        : "=r"(a) : "l"(p));
    return a;
}
__device__ __forceinline__ u64 pack2f(float lo, float hi) {
    u64 r; asm("mov.b64 %0,{%1,%2};" : "=l"(r) : "f"(lo), "f"(hi)); return r;
}
__device__ __forceinline__ float2 unpack2f(u64 v) {
    float2 f; asm("mov.b64 {%0,%1},%2;" : "=f"(f.x), "=f"(f.y) : "l"(v)); return f;
}
__device__ __forceinline__ u64 ffma2(u64 a, u64 b, u64 c) {
    u64 d; asm("fma.rn.f32x2 %0,%1,%2,%3;" : "=l"(d) : "l"(a), "l"(b), "l"(c)); return d;
}
__device__ __forceinline__ u64 mul2(u64 a, u64 b) {
    return ffma2(a, b, 0ull);   // (0.0f,0.0f) addend; fma form is known-good on compute_103
}
// packed powers: e2[k] = (r^(2k+1), r^(2k+2)), k=0..7
__device__ __forceinline__ void pow16p(float r, u64* e2) {
    const float r2 = r * r, r4 = r2 * r2, r8 = r4 * r4;
    const u64 r2p = pack2f(r2, r2);
    const u64 r4p = pack2f(r4, r4);
    const u64 r8p = pack2f(r8, r8);
    e2[0] = pack2f(r, r2);
    e2[1] = mul2(e2[0], r2p);
    e2[2] = mul2(e2[0], r4p);
    e2[3] = mul2(e2[1], r4p);
    e2[4] = mul2(e2[0], r8p);
    e2[5] = mul2(e2[1], r8p);
    e2[6] = mul2(e2[2], r8p);
    e2[7] = mul2(e2[3], r8p);
}
union F4U2 { float4 f4; u64 u2[2]; };

__device__ __forceinline__ void split2(float a, float b, unsigned& h, unsigned& l) {
    __nv_bfloat16 ha = __float2bfloat16(a), hb = __float2bfloat16(b);
    float ra = a - __bfloat162float(ha), rb = b - __bfloat162float(hb);
    __nv_bfloat16 la = __float2bfloat16(ra), lb = __float2bfloat16(rb);
    h = (unsigned)__bfloat16_as_ushort(ha) | ((unsigned)__bfloat16_as_ushort(hb) << 16);
    l = (unsigned)__bfloat16_as_ushort(la) | ((unsigned)__bfloat16_as_ushort(lb) << 16);
}
__device__ __forceinline__ void splitf4(float4 v, uint2& h, uint2& l) {
    split2(v.x, v.y, h.x, l.x);
    split2(v.z, v.w, h.y, l.y);
}
__device__ __forceinline__ void ldsm_x4(unsigned* a, unsigned addr) {
    asm volatile("ldmatrix.sync.aligned.m8n8.x4.shared.b16 {%0,%1,%2,%3}, [%4];"
        : "=r"(a[0]), "=r"(a[1]), "=r"(a[2]), "=r"(a[3]) : "r"(addr));
}
__device__ __forceinline__ void ldsm_x2(unsigned* a, unsigned addr) {
    asm volatile("ldmatrix.sync.aligned.m8n8.x2.shared.b16 {%0,%1}, [%2];"
        : "=r"(a[0]), "=r"(a[1]) : "r"(addr));
}
__device__ __forceinline__ void mma_bf16(float* c, const unsigned* a, const unsigned* b) {
    asm volatile(
        "mma.sync.aligned.m16n8k16.row.col.f32.bf16.bf16.f32 "
        "{%0,%1,%2,%3},{%4,%5,%6,%7},{%8,%9},{%0,%1,%2,%3};"
        : "+f"(c[0]), "+f"(c[1]), "+f"(c[2]), "+f"(c[3])
        : "r"(a[0]), "r"(a[1]), "r"(a[2]), "r"(a[3]), "r"(b[0]), "r"(b[1]));
}

// ---------------------------------------------------------------------------
// PREP (unchanged)
// ---------------------------------------------------------------------------
__global__ __launch_bounds__(256) void prep_kernel(
    const float* __restrict__ W1, const float* __restrict__ Wd)
{
    const int id = blockIdx.x * 256 + threadIdx.x;
    if (id < 81920) {
        const int r = id >> 9, c4 = id & 511;
        float4 v = *(const float4*)(W1 + (size_t)r * DIN + c4 * 4);
        uint2 h, l; splitf4(v, h, l);
        *(uint2*)(g_w1h + (size_t)r * DIN + c4 * 4) = h;
        *(uint2*)(g_w1l + (size_t)r * DIN + c4 * 4) = l;
    } else {
        const int id2 = id - 81920;
        const int r = id2 >> 5, c4 = id2 & 31;
        float4 v = *(const float4*)(Wd + (size_t)r * RNK + c4 * 4);
        uint2 h, l; splitf4(v, h, l);
        *(uint2*)(g_wdh + (size_t)r * RNK + c4 * 4) = h;
        *(uint2*)(g_wdl + (size_t)r * RNK + c4 * 4) = l;
    }
}

// ---------------------------------------------------------------------------
// GEMM1 (unchanged)
// ---------------------------------------------------------------------------
#define G1_AH 0
#define G1_AL 5120
#define G1_BH 10240
#define G1_BL 23040
#define G1_BUF 35840
#define G1_SMEM (2*G1_BUF)

__global__ __launch_bounds__(256, 2) void gemm1_kernel(const float* __restrict__ X)
{
    extern __shared__ __align__(16) char smem[];
    const unsigned sb = smem_u32(smem);
    const int tid = threadIdx.x, lane = tid & 31, w = tid >> 5;
    const int m0 = blockIdx.x * 64;
    const int wm = (w & 1) * 32;
    const int wn = (w >> 1) * 40;

    float acc[2][5][4];
#pragma unroll
    for (int i = 0; i < 2; i++)
#pragma unroll
        for (int j = 0; j < 5; j++)
#pragma unroll
            for (int q = 0; q < 4; q++) acc[i][j][q] = 0.f;

    const int rX0 = tid >> 3, cX0 = (tid & 7) * 4;
    const int rX1 = (tid + 256) >> 3, cX1 = cX0;

    float4 xr[2]; uint4 wr[5];

    auto load_regs = [&](int k0) {
        xr[0] = *(const float4*)(X + (size_t)(m0 + rX0) * DIN + k0 + cX0);
        xr[1] = *(const float4*)(X + (size_t)(m0 + rX1) * DIN + k0 + cX1);
#pragma unroll
        for (int q = 0; q < 5; q++) {
            const int id = q * 256 + tid;
            const __nv_bfloat16* src = (id < 640) ? g_w1h : g_w1l;
            const int rid = (id < 640) ? id : id - 640;
            const int r = rid >> 2, c16 = rid & 3;
            wr[q] = *(const uint4*)(src + (size_t)r * DIN + k0 + c16 * 8);
        }
    };
    auto store_smem = [&](int bi) {
        char* buf = smem + bi * G1_BUF;
        {
            uint2 h, l; splitf4(xr[0], h, l);
            *(uint2*)(buf + G1_AH + 80 * rX0 + 2 * cX0) = h;
            *(uint2*)(buf + G1_AL + 80 * rX0 + 2 * cX0) = l;
            splitf4(xr[1], h, l);
            *(uint2*)(buf + G1_AH + 80 * rX1 + 2 * cX1) = h;
            *(uint2*)(buf + G1_AL + 80 * rX1 + 2 * cX1) = l;
        }
#pragma unroll
        for (int q = 0; q < 5; q++) {
            const int id = q * 256 + tid;
            const int off = (id < 640) ? G1_BH : G1_BL;
            const int rid = (id < 640) ? id : id - 640;
            const int r = rid >> 2, c16 = rid & 3;
            *(uint4*)(buf + off + 80 * r + 16 * c16) = wr[q];
        }
    };
    auto compute = [&](int bi) {
        const unsigned base = sb + bi * G1_BUF;
#pragma unroll
        for (int ks = 0; ks < 2; ks++) {
            const int kc = ks * 16 + ((lane >> 4) & 1) * 8;
            unsigned ah[2][4], al[2][4];
#pragma unroll
            for (int mt = 0; mt < 2; mt++) {
                const int row = wm + mt * 16 + (lane & 15);
                const unsigned ad = base + 80u * row + 2u * kc;
                ldsm_x4(ah[mt], ad + G1_AH);
                ldsm_x4(al[mt], ad + G1_AL);
            }
            unsigned bh[5][2], bl[5][2];
#pragma unroll
            for (int nt = 0; nt < 5; nt++) {
                const int row = wn + nt * 8 + (lane & 7);
                const int col = ks * 16 + ((lane >> 3) & 1) * 8;
                const unsigned bd = base + 80u * row + 2u * col;
                ldsm_x2(bh[nt], bd + G1_BH);
                ldsm_x2(bl[nt], bd + G1_BL);
            }
#pragma unroll
            for (int mt = 0; mt < 2; mt++)
#pragma unroll
                for (int nt = 0; nt < 5; nt++) {
                    mma_bf16(acc[mt][nt], ah[mt], bh[nt]);
                    mma_bf16(acc[mt][nt], ah[mt], bl[nt]);
                    mma_bf16(acc[mt][nt], al[mt], bh[nt]);
                }
        }
    };

    load_regs(0);
    store_smem(0);
    __syncthreads();
    for (int it = 0; it < 64; it++) {
        if (it + 1 < 64) load_regs((it + 1) * 32);
        compute(it & 1);
        if (it + 1 < 64) {
            __syncthreads();
            store_smem((it + 1) & 1);
            __syncthreads();
        }
    }

#pragma unroll
    for (int mt = 0; mt < 2; mt++) {
#pragma unroll
        for (int nt = 0; nt < 5; nt++) {
            const int cb = wn + nt * 8 + 2 * (lane & 3);
            const int mA = m0 + wm + mt * 16 + (lane >> 2);
            const float* c = acc[mt][nt];
            if (cb < RNK) {
                unsigned h, l;
                split2(c[0], c[1], h, l);
                *(unsigned*)(g_dth + (size_t)mA * RNK + cb) = h;
                *(unsigned*)(g_dtl + (size_t)mA * RNK + cb) = l;
                split2(c[2], c[3], h, l);
                *(unsigned*)(g_dth + (size_t)(mA + 8) * RNK + cb) = h;
                *(unsigned*)(g_dtl + (size_t)(mA + 8) * RNK + cb) = l;
            } else if (cb < RNK + NST) {
                *(float2*)(g_B + (size_t)mA * NST + (cb - RNK)) = make_float2(c[0], c[1]);
                *(float2*)(g_B + (size_t)(mA + 8) * NST + (cb - RNK)) = make_float2(c[2], c[3]);
            } else {
                *(float2*)(g_C + (size_t)mA * NST + (cb - RNK - NST)) = make_float2(c[0], c[1]);
                *(float2*)(g_C + (size_t)(mA + 8) * NST + (cb - RNK - NST)) = make_float2(c[2], c[3]);
            }
        }
    }
}

// ---------------------------------------------------------------------------
// GEMM2 (unchanged)
// ---------------------------------------------------------------------------
#define G2_AH 0
#define G2_AL 17408
#define G2_BH 34816
#define G2_BL 69632
#define G2_SMEM 104448

__global__ __launch_bounds__(256, 2) void gemm2_kernel(const float* __restrict__ bias)
{
    extern __shared__ __align__(16) char smem[];
    const unsigned sb = smem_u32(smem);
    const int tid = threadIdx.x, lane = tid & 31, w = tid >> 5;
    const int mt_ = blockIdx.x >> 4;
    const int nt_ = blockIdx.x & 15;
    const int m0 = mt_ * 64, d0 = nt_ * 128;
    const int wm = (w & 1) * 32;
    const int wn = (w >> 1) * 32;

#pragma unroll
    for (int q = 0; q < 8; q++) {
        const int id = q * 256 + tid;
        const __nv_bfloat16* src = (id < 1024) ? g_dth : g_dtl;
        const int off = (id < 1024) ? G2_AH : G2_AL;
        const int rid = id & 1023;
        const int r = rid >> 4, c16 = rid & 15;
        uint4 v = *(const uint4*)(src + (size_t)(m0 + r) * RNK + c16 * 8);
        *(uint4*)(smem + off + 272 * r + 16 * c16) = v;
    }
#pragma unroll
    for (int q = 0; q < 16; q++) {
        const int id = q * 256 + tid;
        const __nv_bfloat16* src = (id < 2048) ? g_wdh : g_wdl;
        const int off = (id < 2048) ? G2_BH : G2_BL;
        const int rid = id & 2047;
        const int r = rid >> 4, c16 = rid & 15;
        uint4 v = *(const uint4*)(src + (size_t)(d0 + r) * RNK + c16 * 8);
        *(uint4*)(smem + off + 272 * r + 16 * c16) = v;
    }
    __syncthreads();

    float acc[2][4][4];
#pragma unroll
    for (int i = 0; i < 2; i++)
#pragma unroll
        for (int j = 0; j < 4; j++)
#pragma unroll
            for (int q = 0; q < 4; q++) acc[i][j][q] = 0.f;

#pragma unroll
    for (int ks = 0; ks < 8; ks++) {
        const int kc = ks * 16 + ((lane >> 4) & 1) * 8;
        unsigned ah[2][4], al[2][4];
#pragma unroll
        for (int mt = 0; mt < 2; mt++) {
            const int row = wm + mt * 16 + (lane & 15);
            const unsigned ad = sb + 272u * row + 2u * kc;
            ldsm_x4(ah[mt], ad + G2_AH);
            ldsm_x4(al[mt], ad + G2_AL);
        }
        unsigned bh[4][2], bl[4][2];
#pragma unroll
        for (int nt = 0; nt < 4; nt++) {
            const int row = wn + nt * 8 + (lane & 7);
            const int col = ks * 16 + ((lane >> 3) & 1) * 8;
            const unsigned bd = sb + 272u * row + 2u * col;
            ldsm_x2(bh[nt], bd + G2_BH);
            ldsm_x2(bl[nt], bd + G2_BL);
        }
#pragma unroll
        for (int mt = 0; mt < 2; mt++)
#pragma unroll
            for (int nt = 0; nt < 4; nt++) {
                mma_bf16(acc[mt][nt], ah[mt], bh[nt]);
                mma_bf16(acc[mt][nt], ah[mt], bl[nt]);
                mma_bf16(acc[mt][nt], al[mt], bh[nt]);
            }
    }

#pragma unroll
    for (int mt = 0; mt < 2; mt++) {
#pragma unroll
        for (int nt = 0; nt < 4; nt++) {
            const int d = d0 + wn + nt * 8 + 2 * (lane & 3);
            const int mA = m0 + wm + mt * 16 + (lane >> 2);
            const float b0v = bias[d], b1v = bias[d + 1];
            const float* c = acc[mt][nt];
            float z0 = c[0] + b0v, z1 = c[1] + b1v;
            float z2 = c[2] + b0v, z3 = c[3] + b1v;
            z0 = (z0 > 20.f) ? z0 : log1pf(__expf(z0));
            z1 = (z1 > 20.f) ? z1 : log1pf(__expf(z1));
            z2 = (z2 > 20.f) ? z2 : log1pf(__expf(z2));
            z3 = (z3 > 20.f) ? z3 : log1pf(__expf(z3));
            *(float2*)(g_delta + (size_t)mA * DIN + d) = make_float2(z0, z1);
            *(float2*)(g_delta + (size_t)(mA + 8) * DIN + d) = make_float2(z2, z3);
        }
    }
}

// ---------------------------------------------------------------------------
// Scan v6: 1 thread/channel, 16 states as 8 packed f32x2 registers.
// Fast path: 1 MUFU + packed power tree + 8 mul2 + 8 fma2 per step.
// Slow path (never taken for this dataset) reloads A from gmem per chunk.
// ---------------------------------------------------------------------------
__device__ __forceinline__ void load_A16(const float* A_log, int d, float* A) {
#pragma unroll
    for (int q = 0; q < 4; q++) {
        float4 v = *(const float4*)(A_log + (size_t)d * NST + 4 * q);
        A[4*q+0] = -__expf(v.x); A[4*q+1] = -__expf(v.y);
        A[4*q+2] = -__expf(v.z); A[4*q+3] = -__expf(v.w);
    }
}

__global__ __launch_bounds__(CPB) void scan_seg1_kernel(
    const float* __restrict__ x, const float* __restrict__ A_log)
{
    __shared__ __align__(16) float xs [SCH][CPB];
    __shared__ __align__(16) float dsm[SCH][CPB];
    __shared__ __align__(16) float Bs [SCH][16];

    const int tid  = threadIdx.x;
    const int dg   = blockIdx.x & 15;
    const int bseg = blockIdx.x >> 4;
    const int b    = bseg >> 4;
    const int seg  = bseg & 15;
    const int d    = dg * CPB + tid;

    unsigned fast;
    {
        float A[16];
        load_A16(A_log, d, A);
        bool ok = fabsf(A[0] + 1.f) < 2e-3f;
#pragma unroll
        for (int i = 1; i < 16; i++) ok = ok && (fabsf(A[i] - A[i-1] + 1.f) < 2e-3f);
        fast = __all_sync(0xffffffffu, ok);
    }

    const size_t t0 = (size_t)b * LEN + (size_t)seg * SEGLEN;
    const float* xg  = x       + t0 * DIN + dg * CPB;
    const float* dgp = g_delta + t0 * DIN + dg * CPB;
    const float* Bg  = g_B     + t0 * NST;

    const int rA = tid >> 5;
    const int qA = (tid & 31) * 4;
    const int rB = (tid & 63) >> 2;
    const int qB = (tid & 3) * 4;

    u64 h2[8];
#pragma unroll
    for (int i = 0; i < 8; i++) h2[i] = 0ull;
    float Sd = 0.f;

    float4 px[4], pd[4], pb;
#pragma unroll
    for (int q = 0; q < 4; q++) {
        px[q] = *(const float4*)(xg  + (size_t)(rA + 4 * q) * DIN + qA);
        pd[q] = *(const float4*)(dgp + (size_t)(rA + 4 * q) * DIN + qA);
    }
    if (tid < 64) pb = *(const float4*)(Bg + (size_t)rB * NST + qB);
#pragma unroll
    for (int q = 0; q < 4; q++) {
        *(float4*)&xs [rA + 4 * q][qA] = px[q];
        *(float4*)&dsm[rA + 4 * q][qA] = pd[q];
    }
    if (tid < 64) *(float4*)&Bs[rB][qB] = pb;
    __syncthreads();

    for (int c = 0; c < NCHS; c++) {
        if (c + 1 < NCHS) {
            const size_t off = (size_t)(c + 1) * SCH;
#pragma unroll
            for (int q = 0; q < 4; q++) {
                px[q] = *(const float4*)(xg  + (off + rA + 4 * q) * DIN + qA);
                pd[q] = *(const float4*)(dgp + (off + rA + 4 * q) * DIN + qA);
            }
            if (tid < 64) pb = *(const float4*)(Bg + (off + rB) * NST + qB);
        }

        if (fast) {
#pragma unroll
            for (int j = 0; j < SCH; j++) {
                const float dv = dsm[j][tid];
                const float xv = xs [j][tid];
                F4U2 bb[4];
#pragma unroll
                for (int q = 0; q < 4; q++) bb[q].f4 = *(const float4*)&Bs[j][4 * q];
                const float r = __expf(-dv);
                const float s = dv * xv;
                Sd += dv;
                const u64 s2 = pack2f(s, s);
                u64 e2[8]; pow16p(r, e2);
#pragma unroll
                for (int i = 0; i < 8; i++)
                    h2[i] = ffma2(e2[i], h2[i], mul2(s2, bb[i >> 1].u2[i & 1]));
            }
        } else {
            float A[16];
            load_A16(A_log, d, A);
#pragma unroll
            for (int j = 0; j < SCH; j++) {
                const float dv = dsm[j][tid];
                const float xv = xs [j][tid];
                float Bv[16];
#pragma unroll
                for (int q = 0; q < 4; q++)
                    *(float4*)&Bv[4 * q] = *(const float4*)&Bs[j][4 * q];
                const float s = dv * xv;
                Sd += dv;
#pragma unroll
                for (int i = 0; i < 8; i++) {
                    float2 hh = unpack2f(h2[i]);
                    hh.x = fmaf(__expf(dv * A[2*i]),   hh.x, s * Bv[2*i]);
                    hh.y = fmaf(__expf(dv * A[2*i+1]), hh.y, s * Bv[2*i+1]);
                    h2[i] = pack2f(hh.x, hh.y);
                }
            }
        }
        __syncthreads();
        if (c + 1 < NCHS) {
#pragma unroll
            for (int q = 0; q < 4; q++) {
                *(float4*)&xs [rA + 4 * q][qA] = px[q];
                *(float4*)&dsm[rA + 4 * q][qA] = pd[q];
            }
            if (tid < 64) *(float4*)&Bs[rB][qB] = pb;
        }
        __syncthreads();
    }

    u64 p2[8];
    if (fast) {
        pow16p(__expf(-Sd), p2);
    } else {
        float A[16];
        load_A16(A_log, d, A);
#pragma unroll
        for (int i = 0; i < 8; i++)
            p2[i] = pack2f(__expf(A[2*i] * Sd), __expf(A[2*i+1] * Sd));
    }
    const size_t hb = (((size_t)(b * P_SEG + seg) * DIN) + d) * NST;
#pragma unroll
    for (int q = 0; q < 4; q++) {
        float2 a = unpack2f(h2[2*q]),   bq = unpack2f(h2[2*q+1]);
        *(float4*)(g_hseg + hb + 4 * q) = make_float4(a.x, a.y, bq.x, bq.y);
        a = unpack2f(p2[2*q]); bq = unpack2f(p2[2*q+1]);
        *(float4*)(g_pseg + hb + 4 * q) = make_float4(a.x, a.y, bq.x, bq.y);
    }
}

__global__ __launch_bounds__(256) void scan_comb_kernel()
{
    const int tid  = threadIdx.x;
    const int cidx = blockIdx.x * 64 + (tid >> 2);
    const int ng   = tid & 3;
    const int b    = cidx >> 11;
    const int d    = cidx & (DIN - 1);

    float4 h = make_float4(0.f, 0.f, 0.f, 0.f);
#pragma unroll
    for (int s = 0; s < P_SEG; s++) {
        const size_t idx = (((size_t)(b * P_SEG + s) * DIN) + d) * NST + 4 * ng;
        *(float4*)(g_hin + idx) = h;
        const float4 Pv = *(const float4*)(g_pseg + idx);
        const float4 Lv = *(const float4*)(g_hseg + idx);
        h.x = fmaf(Pv.x, h.x, Lv.x);
        h.y = fmaf(Pv.y, h.y, Lv.y);
        h.z = fmaf(Pv.z, h.z, Lv.z);
        h.w = fmaf(Pv.w, h.w, Lv.w);
    }
}

__global__ __launch_bounds__(CPB) void scan_seg2_kernel(
    const float* __restrict__ x, const float* __restrict__ A_log,
    const float* __restrict__ Dpar, float* __restrict__ out)
{
    __shared__ __align__(16) float xs [SCH][CPB];
    __shared__ __align__(16) float dsm[SCH][CPB];
    __shared__ __align__(16) float ys [SCH][CPB];
    __shared__ __align__(16) float Bs [SCH][16];
    __shared__ __align__(16) float Cs [SCH][16];

    const int tid  = threadIdx.x;
    const int dg   = blockIdx.x & 15;
    const int bseg = blockIdx.x >> 4;
    const int b    = bseg >> 4;
    const int seg  = bseg & 15;
    const int d    = dg * CPB + tid;

    unsigned fast;
    {
        float A[16];
        load_A16(A_log, d, A);
        bool ok = fabsf(A[0] + 1.f) < 2e-3f;
#pragma unroll
        for (int i = 1; i < 16; i++) ok = ok && (fabsf(A[i] - A[i-1] + 1.f) < 2e-3f);
        fast = __all_sync(0xffffffffu, ok);
    }
    const float Dd = Dpar[d];

    const size_t t0 = (size_t)b * LEN + (size_t)seg * SEGLEN;
    const float* xg  = x       + t0 * DIN + dg * CPB;
    const float* dgp = g_delta + t0 * DIN + dg * CPB;
    const float* Bg  = g_B     + t0 * NST;
    const float* Cg  = g_C     + t0 * NST;
    float*       og  = out     + t0 * DIN + dg * CPB;

    const int rA = tid >> 5;
    const int qA = (tid & 31) * 4;
    const int rB = (tid & 63) >> 2;
    const int qB = (tid & 3) * 4;

    u64 h2[8];
    const size_t hb = (((size_t)(b * P_SEG + seg) * DIN) + d) * NST;
#pragma unroll
    for (int q = 0; q < 4; q++) {
        F4U2 t; t.f4 = *(const float4*)(g_hin + hb + 4 * q);
        h2[2*q]   = t.u2[0];
        h2[2*q+1] = t.u2[1];
    }

    float4 px[4], pd[4], pbc;
#pragma unroll
    for (int q = 0; q < 4; q++) {
        px[q] = *(const float4*)(xg  + (size_t)(rA + 4 * q) * DIN + qA);
        pd[q] = *(const float4*)(dgp + (size_t)(rA + 4 * q) * DIN + qA);
    }
    if (tid < 64)       pbc = *(const float4*)(Bg + (size_t)rB * NST + qB);
    else                pbc = *(const float4*)(Cg + (size_t)rB * NST + qB);
#pragma unroll
    for (int q = 0; q < 4; q++) {
        *(float4*)&xs [rA + 4 * q][qA] = px[q];
        *(float4*)&dsm[rA + 4 * q][qA] = pd[q];
    }
    if (tid < 64) *(float4*)&Bs[rB][qB] = pbc;
    else          *(float4*)&Cs[rB][qB] = pbc;
    __syncthreads();

    for (int c = 0; c < NCHS; c++) {
        if (c + 1 < NCHS) {
            const size_t off = (size_t)(c + 1) * SCH;
#pragma unroll
            for (int q = 0; q < 4; q++) {
                px[q] = *(const float4*)(xg  + (off + rA + 4 * q) * DIN + qA);
                pd[q] = *(const float4*)(dgp + (off + rA + 4 * q) * DIN + qA);
            }
            if (tid < 64) pbc = *(const float4*)(Bg + (off + rB) * NST + qB);
            else          pbc = *(const float4*)(Cg + (off + rB) * NST + qB);
        }

        if (fast) {
#pragma unroll
            for (int j = 0; j < SCH; j++) {
                const float dv = dsm[j][tid];
                const float xv = xs [j][tid];
                F4U2 bb[4], cc[4];
#pragma unroll
                for (int q = 0; q < 4; q++) {
                    bb[q].f4 = *(const float4*)&Bs[j][4 * q];
                    cc[q].f4 = *(const float4*)&Cs[j][4 * q];
                }
                const float r = __expf(-dv);
                const float s = dv * xv;
                const u64 s2 = pack2f(s, s);
                u64 e2[8]; pow16p(r, e2);
                u64 y2 = 0ull;
#pragma unroll
                for (int i = 0; i < 8; i++) {
                    h2[i] = ffma2(e2[i], h2[i], mul2(s2, bb[i >> 1].u2[i & 1]));
                    y2 = ffma2(h2[i], cc[i >> 1].u2[i & 1], y2);
                }
                const float2 yy = unpack2f(y2);
                ys[j][tid] = fmaf(Dd, xv, yy.x + yy.y);
            }
        } else {
            float A[16];
            load_A16(A_log, d, A);
#pragma unroll
            for (int j = 0; j < SCH; j++) {
                const float dv = dsm[j][tid];
                const float xv = xs [j][tid];
                float Bv[16], Cv[16];
#pragma unroll
                for (int q = 0; q < 4; q++) {
                    *(float4*)&Bv[4 * q] = *(const float4*)&Bs[j][4 * q];
                    *(float4*)&Cv[4 * q] = *(const float4*)&Cs[j][4 * q];
                }
                const float s = dv * xv;
                float y = 0.f;
#pragma unroll
                for (int i = 0; i < 8; i++) {
                    float2 hh = unpack2f(h2[i]);
                    hh.x = fmaf(__expf(dv * A[2*i]),   hh.x, s * Bv[2*i]);
                    hh.y = fmaf(__expf(dv * A[2*i+1]), hh.y, s * Bv[2*i+1]);
                    y = fmaf(hh.x, Cv[2*i], y);
                    y = fmaf(hh.y, Cv[2*i+1], y);
                    h2[i] = pack2f(hh.x, hh.y);
                }
                ys[j][tid] = fmaf(Dd, xv, y);
            }
        }
        __syncthreads();
        {
            const size_t off = (size_t)c * SCH;
#pragma unroll
            for (int q = 0; q < 4; q++)
                *(float4*)(og + (off + rA + 4 * q) * DIN + qA) =
                    *(const float4*)&ys[rA + 4 * q][qA];
        }
        if (c + 1 < NCHS) {
#pragma unroll
            for (int q = 0; q < 4; q++) {
                *(float4*)&xs [rA + 4 * q][qA] = px[q];
                *(float4*)&dsm[rA + 4 * q][qA] = pd[q];
            }
            if (tid < 64) *(float4*)&Bs[rB][qB] = pbc;
            else          *(float4*)&Cs[rB][qB] = pbc;
        }
        __syncthreads();
    }
}

// ---------------------------------------------------------------------------
// Launch
// ---------------------------------------------------------------------------
extern "C" void kernel_launch(void* const* d_in, const int* in_sizes, int n_in,
                              void* d_out, int out_size)
{
    const float* x         = (const float*)d_in[0];
    const float* A_log     = (const float*)d_in[1];
    const float* D_param   = (const float*)d_in[2];
    const float* x_proj_w  = (const float*)d_in[3];
    const float* dt_proj_w = (const float*)d_in[4];
    const float* dt_proj_b = (const float*)d_in[5];
    float* out = (float*)d_out;

    cudaFuncSetAttribute(gemm1_kernel, cudaFuncAttributeMaxDynamicSharedMemorySize, G1_SMEM);
    cudaFuncSetAttribute(gemm2_kernel, cudaFuncAttributeMaxDynamicSharedMemorySize, G2_SMEM);

    prep_kernel<<<576, 256>>>(x_proj_w, dt_proj_w);
    gemm1_kernel<<<M_TOT / 64, 256, G1_SMEM>>>(x);
    gemm2_kernel<<<(M_TOT / 64) * (DIN / 128), 256, G2_SMEM>>>(dt_proj_b);
    scan_seg1_kernel<<<BATCH * P_SEG * (DIN / CPB), CPB>>>(x, A_log);
    scan_comb_kernel<<<BATCH * DIN / 64, 256>>>();
    scan_seg2_kernel<<<BATCH * P_SEG * (DIN / CPB), CPB>>>(x, A_log, D_param, out);
}

// round 11
// speedup vs baseline: 3.0140x; 1.0236x over previous
#include <cuda_runtime.h>
#include <cuda_bf16.h>
#include <math.h>
#include <stdint.h>

#define BATCH 4
#define LEN   4096
#define DIN   2048
#define NST   16
#define RNK   128
#define M_TOT (BATCH*LEN)   // 16384
#define SCH   16
#define P_SEG 16
#define SEGLEN (LEN/P_SEG)  // 256
#define NCHS  (SEGLEN/SCH)  // 16
#define CPB   128           // channels (=threads) per scan block

typedef unsigned long long u64;

// ---------------------------------------------------------------------------
// Device scratch
// ---------------------------------------------------------------------------
__device__ float g_B [(size_t)M_TOT * NST];
__device__ float g_C [(size_t)M_TOT * NST];
__device__ float g_delta[(size_t)M_TOT * DIN];
__device__ float g_hseg[(size_t)BATCH * P_SEG * DIN * NST];
__device__ float g_pseg[(size_t)BATCH * P_SEG * DIN * NST];
__device__ float g_hin [(size_t)BATCH * P_SEG * DIN * NST];
// bf16 hi/lo split operands (row-major, k contiguous)
__device__ __nv_bfloat16 g_w1h[(size_t)160 * DIN];
__device__ __nv_bfloat16 g_w1l[(size_t)160 * DIN];
__device__ __nv_bfloat16 g_wdh[(size_t)DIN * RNK];
__device__ __nv_bfloat16 g_wdl[(size_t)DIN * RNK];
__device__ __nv_bfloat16 g_dth[(size_t)M_TOT * RNK];
__device__ __nv_bfloat16 g_dtl[(size_t)M_TOT * RNK];

// ---------------------------------------------------------------------------
// helpers
// ---------------------------------------------------------------------------
__device__ __forceinline__ unsigned smem_u32(const void* p) {
    unsigned a;
    asm("{ .reg .u64 t; cvta.to.shared.u64 t, %1; cvt.u32.u64 %0, t; }"
        : "=r"(a) : "l"(p));
    return a;
}
__device__ __forceinline__ u64 pack2f(float lo, float hi) {
    u64 r; asm("mov.b64 %0,{%1,%2};" : "=l"(r) : "f"(lo), "f"(hi)); return r;
}
__device__ __forceinline__ float2 unpack2f(u64 v) {
    float2 f; asm("mov.b64 {%0,%1},%2;" : "=f"(f.x), "=f"(f.y) : "l"(v)); return f;
}
__device__ __forceinline__ u64 ffma2(u64 a, u64 b, u64 c) {
    u64 d; asm("fma.rn.f32x2 %0,%1,%2,%3;" : "=l"(d) : "l"(a), "l"(b), "l"(c)); return d;
}
__device__ __forceinline__ u64 mul2(u64 a, u64 b) {
    return ffma2(a, b, 0ull);
}
// packed powers: e2[k] = (r^(2k+1), r^(2k+2)), k=0..7
__device__ __forceinline__ void pow16p(float r, u64* e2) {
    const float r2 = r * r, r4 = r2 * r2, r8 = r4 * r4;
    const u64 r2p = pack2f(r2, r2);
    const u64 r4p = pack2f(r4, r4);
    const u64 r8p = pack2f(r8, r8);
    e2[0] = pack2f(r, r2);
    e2[1] = mul2(e2[0], r2p);
    e2[2] = mul2(e2[0], r4p);
    e2[3] = mul2(e2[1], r4p);
    e2[4] = mul2(e2[0], r8p);
    e2[5] = mul2(e2[1], r8p);
    e2[6] = mul2(e2[2], r8p);
    e2[7] = mul2(e2[3], r8p);
}
union F4U2 { float4 f4; u64 u2[2]; };

#define CP_ASYNC16(sm, gp) \
    asm volatile("cp.async.cg.shared.global [%0],[%1],16;" :: "r"(sm), "l"(gp) : "memory")
#define CP_COMMIT() asm volatile("cp.async.commit_group;" ::: "memory")
#define CP_WAIT0()  asm volatile("cp.async.wait_group 0;" ::: "memory")

__device__ __forceinline__ void split2(float a, float b, unsigned& h, unsigned& l) {
    __nv_bfloat16 ha = __float2bfloat16(a), hb = __float2bfloat16(b);
    float ra = a - __bfloat162float(ha), rb = b - __bfloat162float(hb);
    __nv_bfloat16 la = __float2bfloat16(ra), lb = __float2bfloat16(rb);
    h = (unsigned)__bfloat16_as_ushort(ha) | ((unsigned)__bfloat16_as_ushort(hb) << 16);
    l = (unsigned)__bfloat16_as_ushort(la) | ((unsigned)__bfloat16_as_ushort(lb) << 16);
}
__device__ __forceinline__ void splitf4(float4 v, uint2& h, uint2& l) {
    split2(v.x, v.y, h.x, l.x);
    split2(v.z, v.w, h.y, l.y);
}
__device__ __forceinline__ void ldsm_x4(unsigned* a, unsigned addr) {
    asm volatile("ldmatrix.sync.aligned.m8n8.x4.shared.b16 {%0,%1,%2,%3}, [%4];"
        : "=r"(a[0]), "=r"(a[1]), "=r"(a[2]), "=r"(a[3]) : "r"(addr));
}
__device__ __forceinline__ void ldsm_x2(unsigned* a, unsigned addr) {
    asm volatile("ldmatrix.sync.aligned.m8n8.x2.shared.b16 {%0,%1}, [%2];"
        : "=r"(a[0]), "=r"(a[1]) : "r"(addr));
}
__device__ __forceinline__ void mma_bf16(float* c, const unsigned* a, const unsigned* b) {
    asm volatile(
        "mma.sync.aligned.m16n8k16.row.col.f32.bf16.bf16.f32 "
        "{%0,%1,%2,%3},{%4,%5,%6,%7},{%8,%9},{%0,%1,%2,%3};"
        : "+f"(c[0]), "+f"(c[1]), "+f"(c[2]), "+f"(c[3])
        : "r"(a[0]), "r"(a[1]), "r"(a[2]), "r"(a[3]), "r"(b[0]), "r"(b[1]));
}

// ---------------------------------------------------------------------------
// PREP (unchanged)
// ---------------------------------------------------------------------------
__global__ __launch_bounds__(256) void prep_kernel(
    const float* __restrict__ W1, const float* __restrict__ Wd)
{
    const int id = blockIdx.x * 256 + threadIdx.x;
    if (id < 81920) {
        const int r = id >> 9, c4 = id & 511;
        float4 v = *(const float4*)(W1 + (size_t)r * DIN + c4 * 4);
        uint2 h, l; splitf4(v, h, l);
        *(uint2*)(g_w1h + (size_t)r * DIN + c4 * 4) = h;
        *(uint2*)(g_w1l + (size_t)r * DIN + c4 * 4) = l;
    } else {
        const int id2 = id - 81920;
        const int r = id2 >> 5, c4 = id2 & 31;
        float4 v = *(const float4*)(Wd + (size_t)r * RNK + c4 * 4);
        uint2 h, l; splitf4(v, h, l);
        *(uint2*)(g_wdh + (size_t)r * RNK + c4 * 4) = h;
        *(uint2*)(g_wdl + (size_t)r * RNK + c4 * 4) = l;
    }
}

// ---------------------------------------------------------------------------
// GEMM1 (unchanged)
// ---------------------------------------------------------------------------
#define G1_AH 0
#define G1_AL 5120
#define G1_BH 10240
#define G1_BL 23040
#define G1_BUF 35840
#define G1_SMEM (2*G1_BUF)

__global__ __launch_bounds__(256, 2) void gemm1_kernel(const float* __restrict__ X)
{
    extern __shared__ __align__(16) char smem[];
    const unsigned sb = smem_u32(smem);
    const int tid = threadIdx.x, lane = tid & 31, w = tid >> 5;
    const int m0 = blockIdx.x * 64;
    const int wm = (w & 1) * 32;
    const int wn = (w >> 1) * 40;

    float acc[2][5][4];
#pragma unroll
    for (int i = 0; i < 2; i++)
#pragma unroll
        for (int j = 0; j < 5; j++)
#pragma unroll
            for (int q = 0; q < 4; q++) acc[i][j][q] = 0.f;

    const int rX0 = tid >> 3, cX0 = (tid & 7) * 4;
    const int rX1 = (tid + 256) >> 3, cX1 = cX0;

    float4 xr[2]; uint4 wr[5];

    auto load_regs = [&](int k0) {
        xr[0] = *(const float4*)(X + (size_t)(m0 + rX0) * DIN + k0 + cX0);
        xr[1] = *(const float4*)(X + (size_t)(m0 + rX1) * DIN + k0 + cX1);
#pragma unroll
        for (int q = 0; q < 5; q++) {
            const int id = q * 256 + tid;
            const __nv_bfloat16* src = (id < 640) ? g_w1h : g_w1l;
            const int rid = (id < 640) ? id : id - 640;
            const int r = rid >> 2, c16 = rid & 3;
            wr[q] = *(const uint4*)(src + (size_t)r * DIN + k0 + c16 * 8);
        }
    };
    auto store_smem = [&](int bi) {
        char* buf = smem + bi * G1_BUF;
        {
            uint2 h, l; splitf4(xr[0], h, l);
            *(uint2*)(buf + G1_AH + 80 * rX0 + 2 * cX0) = h;
            *(uint2*)(buf + G1_AL + 80 * rX0 + 2 * cX0) = l;
            splitf4(xr[1], h, l);
            *(uint2*)(buf + G1_AH + 80 * rX1 + 2 * cX1) = h;
            *(uint2*)(buf + G1_AL + 80 * rX1 + 2 * cX1) = l;
        }
#pragma unroll
        for (int q = 0; q < 5; q++) {
            const int id = q * 256 + tid;
            const int off = (id < 640) ? G1_BH : G1_BL;
            const int rid = (id < 640) ? id : id - 640;
            const int r = rid >> 2, c16 = rid & 3;
            *(uint4*)(buf + off + 80 * r + 16 * c16) = wr[q];
        }
    };
    auto compute = [&](int bi) {
        const unsigned base = sb + bi * G1_BUF;
#pragma unroll
        for (int ks = 0; ks < 2; ks++) {
            const int kc = ks * 16 + ((lane >> 4) & 1) * 8;
            unsigned ah[2][4], al[2][4];
#pragma unroll
            for (int mt = 0; mt < 2; mt++) {
                const int row = wm + mt * 16 + (lane & 15);
                const unsigned ad = base + 80u * row + 2u * kc;
                ldsm_x4(ah[mt], ad + G1_AH);
                ldsm_x4(al[mt], ad + G1_AL);
            }
            unsigned bh[5][2], bl[5][2];
#pragma unroll
            for (int nt = 0; nt < 5; nt++) {
                const int row = wn + nt * 8 + (lane & 7);
                const int col = ks * 16 + ((lane >> 3) & 1) * 8;
                const unsigned bd = base + 80u * row + 2u * col;
                ldsm_x2(bh[nt], bd + G1_BH);
                ldsm_x2(bl[nt], bd + G1_BL);
            }
#pragma unroll
            for (int mt = 0; mt < 2; mt++)
#pragma unroll
                for (int nt = 0; nt < 5; nt++) {
                    mma_bf16(acc[mt][nt], ah[mt], bh[nt]);
                    mma_bf16(acc[mt][nt], ah[mt], bl[nt]);
                    mma_bf16(acc[mt][nt], al[mt], bh[nt]);
                }
        }
    };

    load_regs(0);
    store_smem(0);
    __syncthreads();
    for (int it = 0; it < 64; it++) {
        if (it + 1 < 64) load_regs((it + 1) * 32);
        compute(it & 1);
        if (it + 1 < 64) {
            __syncthreads();
            store_smem((it + 1) & 1);
            __syncthreads();
        }
    }

#pragma unroll
    for (int mt = 0; mt < 2; mt++) {
#pragma unroll
        for (int nt = 0; nt < 5; nt++) {
            const int cb = wn + nt * 8 + 2 * (lane & 3);
            const int mA = m0 + wm + mt * 16 + (lane >> 2);
            const float* c = acc[mt][nt];
            if (cb < RNK) {
                unsigned h, l;
                split2(c[0], c[1], h, l);
                *(unsigned*)(g_dth + (size_t)mA * RNK + cb) = h;
                *(unsigned*)(g_dtl + (size_t)mA * RNK + cb) = l;
                split2(c[2], c[3], h, l);
                *(unsigned*)(g_dth + (size_t)(mA + 8) * RNK + cb) = h;
                *(unsigned*)(g_dtl + (size_t)(mA + 8) * RNK + cb) = l;
            } else if (cb < RNK + NST) {
                *(float2*)(g_B + (size_t)mA * NST + (cb - RNK)) = make_float2(c[0], c[1]);
                *(float2*)(g_B + (size_t)(mA + 8) * NST + (cb - RNK)) = make_float2(c[2], c[3]);
            } else {
                *(float2*)(g_C + (size_t)mA * NST + (cb - RNK - NST)) = make_float2(c[0], c[1]);
                *(float2*)(g_C + (size_t)(mA + 8) * NST + (cb - RNK - NST)) = make_float2(c[2], c[3]);
            }
        }
    }
}

// ---------------------------------------------------------------------------
// GEMM2 (unchanged)
// ---------------------------------------------------------------------------
#define G2_AH 0
#define G2_AL 17408
#define G2_BH 34816
#define G2_BL 69632
#define G2_SMEM 104448

__global__ __launch_bounds__(256, 2) void gemm2_kernel(const float* __restrict__ bias)
{
    extern __shared__ __align__(16) char smem[];
    const unsigned sb = smem_u32(smem);
    const int tid = threadIdx.x, lane = tid & 31, w = tid >> 5;
    const int mt_ = blockIdx.x >> 4;
    const int nt_ = blockIdx.x & 15;
    const int m0 = mt_ * 64, d0 = nt_ * 128;
    const int wm = (w & 1) * 32;
    const int wn = (w >> 1) * 32;

#pragma unroll
    for (int q = 0; q < 8; q++) {
        const int id = q * 256 + tid;
        const __nv_bfloat16* src = (id < 1024) ? g_dth : g_dtl;
        const int off = (id < 1024) ? G2_AH : G2_AL;
        const int rid = id & 1023;
        const int r = rid >> 4, c16 = rid & 15;
        uint4 v = *(const uint4*)(src + (size_t)(m0 + r) * RNK + c16 * 8);
        *(uint4*)(smem + off + 272 * r + 16 * c16) = v;
    }
#pragma unroll
    for (int q = 0; q < 16; q++) {
        const int id = q * 256 + tid;
        const __nv_bfloat16* src = (id < 2048) ? g_wdh : g_wdl;
        const int off = (id < 2048) ? G2_BH : G2_BL;
        const int rid = id & 2047;
        const int r = rid >> 4, c16 = rid & 15;
        uint4 v = *(const uint4*)(src + (size_t)(d0 + r) * RNK + c16 * 8);
        *(uint4*)(smem + off + 272 * r + 16 * c16) = v;
    }
    __syncthreads();

    float acc[2][4][4];
#pragma unroll
    for (int i = 0; i < 2; i++)
#pragma unroll
        for (int j = 0; j < 4; j++)
#pragma unroll
            for (int q = 0; q < 4; q++) acc[i][j][q] = 0.f;

#pragma unroll
    for (int ks = 0; ks < 8; ks++) {
        const int kc = ks * 16 + ((lane >> 4) & 1) * 8;
        unsigned ah[2][4], al[2][4];
#pragma unroll
        for (int mt = 0; mt < 2; mt++) {
            const int row = wm + mt * 16 + (lane & 15);
            const unsigned ad = sb + 272u * row + 2u * kc;
            ldsm_x4(ah[mt], ad + G2_AH);
            ldsm_x4(al[mt], ad + G2_AL);
        }
        unsigned bh[4][2], bl[4][2];
#pragma unroll
        for (int nt = 0; nt < 4; nt++) {
            const int row = wn + nt * 8 + (lane & 7);
            const int col = ks * 16 + ((lane >> 3) & 1) * 8;
            const unsigned bd = sb + 272u * row + 2u * col;
            ldsm_x2(bh[nt], bd + G2_BH);
            ldsm_x2(bl[nt], bd + G2_BL);
        }
#pragma unroll
        for (int mt = 0; mt < 2; mt++)
#pragma unroll
            for (int nt = 0; nt < 4; nt++) {
                mma_bf16(acc[mt][nt], ah[mt], bh[nt]);
                mma_bf16(acc[mt][nt], ah[mt], bl[nt]);
                mma_bf16(acc[mt][nt], al[mt], bh[nt]);
            }
    }

#pragma unroll
    for (int mt = 0; mt < 2; mt++) {
#pragma unroll
        for (int nt = 0; nt < 4; nt++) {
            const int d = d0 + wn + nt * 8 + 2 * (lane & 3);
            const int mA = m0 + wm + mt * 16 + (lane >> 2);
            const float b0v = bias[d], b1v = bias[d + 1];
            const float* c = acc[mt][nt];
            float z0 = c[0] + b0v, z1 = c[1] + b1v;
            float z2 = c[2] + b0v, z3 = c[3] + b1v;
            z0 = (z0 > 20.f) ? z0 : log1pf(__expf(z0));
            z1 = (z1 > 20.f) ? z1 : log1pf(__expf(z1));
            z2 = (z2 > 20.f) ? z2 : log1pf(__expf(z2));
            z3 = (z3 > 20.f) ? z3 : log1pf(__expf(z3));
            *(float2*)(g_delta + (size_t)mA * DIN + d) = make_float2(z0, z1);
            *(float2*)(g_delta + (size_t)(mA + 8) * DIN + d) = make_float2(z2, z3);
        }
    }
}

// ---------------------------------------------------------------------------
// Scan v7: 1 thread/channel, packed f32x2 states, cp.async double-buffered
// smem staging (no prefetch registers), direct coalesced y stores.
// __launch_bounds__(128, 5) -> 5+ CTAs/SM.
// ---------------------------------------------------------------------------
__device__ __forceinline__ void load_A16(const float* A_log, int d, float* A) {
#pragma unroll
    for (int q = 0; q < 4; q++) {
        float4 v = *(const float4*)(A_log + (size_t)d * NST + 4 * q);
        A[4*q+0] = -__expf(v.x); A[4*q+1] = -__expf(v.y);
        A[4*q+2] = -__expf(v.z); A[4*q+3] = -__expf(v.w);
    }
}

__global__ __launch_bounds__(CPB, 5) void scan_seg1_kernel(
    const float* __restrict__ x, const float* __restrict__ A_log)
{
    __shared__ __align__(16) float xs [2][SCH][CPB];
    __shared__ __align__(16) float dsm[2][SCH][CPB];
    __shared__ __align__(16) float Bs [2][SCH][16];

    const int tid  = threadIdx.x;
    const int dg   = blockIdx.x & 15;
    const int bseg = blockIdx.x >> 4;
    const int b    = bseg >> 4;
    const int seg  = bseg & 15;
    const int d    = dg * CPB + tid;

    unsigned fast;
    {
        float A[16];
        load_A16(A_log, d, A);
        bool ok = fabsf(A[0] + 1.f) < 2e-3f;
#pragma unroll
        for (int i = 1; i < 16; i++) ok = ok && (fabsf(A[i] - A[i-1] + 1.f) < 2e-3f);
        fast = __all_sync(0xffffffffu, ok);
    }

    const size_t t0 = (size_t)b * LEN + (size_t)seg * SEGLEN;
    const float* xg  = x       + t0 * DIN + dg * CPB;
    const float* dgp = g_delta + t0 * DIN + dg * CPB;
    const float* Bg  = g_B     + t0 * NST;

    const int rA = tid >> 5;              // rows rA, rA+4, rA+8, rA+12
    const int qA = (tid & 31) * 4;
    const int rB = (tid & 63) >> 2;
    const int qB = (tid & 3) * 4;

    auto issue = [&](int c, int buf) {
        const size_t off = (size_t)c * SCH;
#pragma unroll
        for (int q = 0; q < 4; q++) {
            const int row = rA + 4 * q;
            CP_ASYNC16(smem_u32(&xs [buf][row][qA]), xg  + (off + row) * DIN + qA);
            CP_ASYNC16(smem_u32(&dsm[buf][row][qA]), dgp + (off + row) * DIN + qA);
        }
        if (tid < 64)
            CP_ASYNC16(smem_u32(&Bs[buf][rB][qB]), Bg + (off + rB) * NST + qB);
        CP_COMMIT();
    };

    u64 h2[8];
#pragma unroll
    for (int i = 0; i < 8; i++) h2[i] = 0ull;
    float Sd = 0.f;

    issue(0, 0);
    for (int c = 0; c < NCHS; c++) {
        const int buf = c & 1;
        CP_WAIT0();
        __syncthreads();
        if (c + 1 < NCHS) issue(c + 1, buf ^ 1);

        if (fast) {
#pragma unroll
            for (int j = 0; j < SCH; j++) {
                const float dv = dsm[buf][j][tid];
                const float xv = xs [buf][j][tid];
                F4U2 bb[4];
#pragma unroll
                for (int q = 0; q < 4; q++) bb[q].f4 = *(const float4*)&Bs[buf][j][4 * q];
                const float r = __expf(-dv);
                const float s = dv * xv;
                Sd += dv;
                const u64 s2 = pack2f(s, s);
                u64 e2[8]; pow16p(r, e2);
#pragma unroll
                for (int i = 0; i < 8; i++)
                    h2[i] = ffma2(e2[i], h2[i], mul2(s2, bb[i >> 1].u2[i & 1]));
            }
        } else {
            float A[16];
            load_A16(A_log, d, A);
#pragma unroll
            for (int j = 0; j < SCH; j++) {
                const float dv = dsm[buf][j][tid];
                const float xv = xs [buf][j][tid];
                float Bv[16];
#pragma unroll
                for (int q = 0; q < 4; q++)
                    *(float4*)&Bv[4 * q] = *(const float4*)&Bs[buf][j][4 * q];
                const float s = dv * xv;
                Sd += dv;
#pragma unroll
                for (int i = 0; i < 8; i++) {
                    float2 hh = unpack2f(h2[i]);
                    hh.x = fmaf(__expf(dv * A[2*i]),   hh.x, s * Bv[2*i]);
                    hh.y = fmaf(__expf(dv * A[2*i+1]), hh.y, s * Bv[2*i+1]);
                    h2[i] = pack2f(hh.x, hh.y);
                }
            }
        }
    }

    u64 p2[8];
    if (fast) {
        pow16p(__expf(-Sd), p2);
    } else {
        float A[16];
        load_A16(A_log, d, A);
#pragma unroll
        for (int i = 0; i < 8; i++)
            p2[i] = pack2f(__expf(A[2*i] * Sd), __expf(A[2*i+1] * Sd));
    }
    const size_t hb = (((size_t)(b * P_SEG + seg) * DIN) + d) * NST;
#pragma unroll
    for (int q = 0; q < 4; q++) {
        float2 a = unpack2f(h2[2*q]),   bq = unpack2f(h2[2*q+1]);
        *(float4*)(g_hseg + hb + 4 * q) = make_float4(a.x, a.y, bq.x, bq.y);
        a = unpack2f(p2[2*q]); bq = unpack2f(p2[2*q+1]);
        *(float4*)(g_pseg + hb + 4 * q) = make_float4(a.x, a.y, bq.x, bq.y);
    }
}

__global__ __launch_bounds__(256) void scan_comb_kernel()
{
    const int tid  = threadIdx.x;
    const int cidx = blockIdx.x * 64 + (tid >> 2);
    const int ng   = tid & 3;
    const int b    = cidx >> 11;
    const int d    = cidx & (DIN - 1);

    float4 h = make_float4(0.f, 0.f, 0.f, 0.f);
#pragma unroll
    for (int s = 0; s < P_SEG; s++) {
        const size_t idx = (((size_t)(b * P_SEG + s) * DIN) + d) * NST + 4 * ng;
        *(float4*)(g_hin + idx) = h;
        const float4 Pv = *(const float4*)(g_pseg + idx);
        const float4 Lv = *(const float4*)(g_hseg + idx);
        h.x = fmaf(Pv.x, h.x, Lv.x);
        h.y = fmaf(Pv.y, h.y, Lv.y);
        h.z = fmaf(Pv.z, h.z, Lv.z);
        h.w = fmaf(Pv.w, h.w, Lv.w);
    }
}

__global__ __launch_bounds__(CPB, 5) void scan_seg2_kernel(
    const float* __restrict__ x, const float* __restrict__ A_log,
    const float* __restrict__ Dpar, float* __restrict__ out)
{
    __shared__ __align__(16) float xs [2][SCH][CPB];
    __shared__ __align__(16) float dsm[2][SCH][CPB];
    __shared__ __align__(16) float Bs [2][SCH][16];
    __shared__ __align__(16) float Cs [2][SCH][16];

    const int tid  = threadIdx.x;
    const int dg   = blockIdx.x & 15;
    const int bseg = blockIdx.x >> 4;
    const int b    = bseg >> 4;
    const int seg  = bseg & 15;
    const int d    = dg * CPB + tid;

    unsigned fast;
    {
        float A[16];
        load_A16(A_log, d, A);
        bool ok = fabsf(A[0] + 1.f) < 2e-3f;
#pragma unroll
        for (int i = 1; i < 16; i++) ok = ok && (fabsf(A[i] - A[i-1] + 1.f) < 2e-3f);
        fast = __all_sync(0xffffffffu, ok);
    }
    const float Dd = Dpar[d];

    const size_t t0 = (size_t)b * LEN + (size_t)seg * SEGLEN;
    const float* xg  = x       + t0 * DIN + dg * CPB;
    const float* dgp = g_delta + t0 * DIN + dg * CPB;
    const float* Bg  = g_B     + t0 * NST;
    const float* Cg  = g_C     + t0 * NST;
    float*       og  = out     + t0 * DIN + dg * CPB + tid;

    const int rA = tid >> 5;
    const int qA = (tid & 31) * 4;
    const int rB = (tid & 63) >> 2;
    const int qB = (tid & 3) * 4;

    auto issue = [&](int c, int buf) {
        const size_t off = (size_t)c * SCH;
#pragma unroll
        for (int q = 0; q < 4; q++) {
            const int row = rA + 4 * q;
            CP_ASYNC16(smem_u32(&xs [buf][row][qA]), xg  + (off + row) * DIN + qA);
            CP_ASYNC16(smem_u32(&dsm[buf][row][qA]), dgp + (off + row) * DIN + qA);
        }
        if (tid < 64)
            CP_ASYNC16(smem_u32(&Bs[buf][rB][qB]), Bg + (off + rB) * NST + qB);
        else if (tid < 128)
            CP_ASYNC16(smem_u32(&Cs[buf][rB][qB]), Cg + (off + rB) * NST + qB);
        CP_COMMIT();
    };

    u64 h2[8];
    const size_t hb = (((size_t)(b * P_SEG + seg) * DIN) + d) * NST;
#pragma unroll
    for (int q = 0; q < 4; q++) {
        F4U2 t; t.f4 = *(const float4*)(g_hin + hb + 4 * q);
        h2[2*q]   = t.u2[0];
        h2[2*q+1] = t.u2[1];
    }

    issue(0, 0);
    for (int c = 0; c < NCHS; c++) {
        const int buf = c & 1;
        CP_WAIT0();
        __syncthreads();
        if (c + 1 < NCHS) issue(c + 1, buf ^ 1);
        const size_t off = (size_t)c * SCH;

        if (fast) {
#pragma unroll
            for (int j = 0; j < SCH; j++) {
                const float dv = dsm[buf][j][tid];
                const float xv = xs [buf][j][tid];
                F4U2 bb[4], cc[4];
#pragma unroll
                for (int q = 0; q < 4; q++) {
                    bb[q].f4 = *(const float4*)&Bs[buf][j][4 * q];
                    cc[q].f4 = *(const float4*)&Cs[buf][j][4 * q];
                }
                const float r = __expf(-dv);
                const float s = dv * xv;
                const u64 s2 = pack2f(s, s);
                u64 e2[8]; pow16p(r, e2);
                u64 y2 = 0ull;
#pragma unroll
                for (int i = 0; i < 8; i++) {
                    h2[i] = ffma2(e2[i], h2[i], mul2(s2, bb[i >> 1].u2[i & 1]));
                    y2 = ffma2(h2[i], cc[i >> 1].u2[i & 1], y2);
                }
                const float2 yy = unpack2f(y2);
                og[(off + j) * DIN] = fmaf(Dd, xv, yy.x + yy.y);
            }
        } else {
            float A[16];
            load_A16(A_log, d, A);
#pragma unroll
            for (int j = 0; j < SCH; j++) {
                const float dv = dsm[buf][j][tid];
                const float xv = xs [buf][j][tid];
                float Bv[16], Cv[16];
#pragma unroll
                for (int q = 0; q < 4; q++) {
                    *(float4*)&Bv[4 * q] = *(const float4*)&Bs[buf][j][4 * q];
                    *(float4*)&Cv[4 * q] = *(const float4*)&Cs[buf][j][4 * q];
                }
                const float s = dv * xv;
                float y = 0.f;
#pragma unroll
                for (int i = 0; i < 8; i++) {
                    float2 hh = unpack2f(h2[i]);
                    hh.x = fmaf(__expf(dv * A[2*i]),   hh.x, s * Bv[2*i]);
                    hh.y = fmaf(__expf(dv * A[2*i+1]), hh.y, s * Bv[2*i+1]);
                    y = fmaf(hh.x, Cv[2*i], y);
                    y = fmaf(hh.y, Cv[2*i+1], y);
                    h2[i] = pack2f(hh.x, hh.y);
                }
                og[(off + j) * DIN] = fmaf(Dd, xv, y);
            }
        }
    }
}

// ---------------------------------------------------------------------------
// Launch
// ---------------------------------------------------------------------------
extern "C" void kernel_launch(void* const* d_in, const int* in_sizes, int n_in,
                              void* d_out, int out_size)
{
    const float* x         = (const float*)d_in[0];
    const float* A_log     = (const float*)d_in[1];
    const float* D_param   = (const float*)d_in[2];
    const float* x_proj_w  = (const float*)d_in[3];
    const float* dt_proj_w = (const float*)d_in[4];
    const float* dt_proj_b = (const float*)d_in[5];
    float* out = (float*)d_out;

    cudaFuncSetAttribute(gemm1_kernel, cudaFuncAttributeMaxDynamicSharedMemorySize, G1_SMEM);
    cudaFuncSetAttribute(gemm2_kernel, cudaFuncAttributeMaxDynamicSharedMemorySize, G2_SMEM);

    prep_kernel<<<576, 256>>>(x_proj_w, dt_proj_w);
    gemm1_kernel<<<M_TOT / 64, 256, G1_SMEM>>>(x);
    gemm2_kernel<<<(M_TOT / 64) * (DIN / 128), 256, G2_SMEM>>>(dt_proj_b);
    scan_seg1_kernel<<<BATCH * P_SEG * (DIN / CPB), CPB>>>(x, A_log);
    scan_comb_kernel<<<BATCH * DIN / 64, 256>>>();
    scan_seg2_kernel<<<BATCH * P_SEG * (DIN / CPB), CPB>>>(x, A_log, D_param, out);
}